// round 1
// baseline (speedup 1.0000x reference)
#include <cuda_runtime.h>

#define NNODES 20000
#define NEDGES 320000
#define NEPLUS 340000   // edges + self loops
#define NGRAPH 256
#define SCAN_BLOCKS 79  // ceil(20000/256)

// ---------------- scratch (device globals; no runtime alloc allowed) ----------------
__device__ float g_feat[NNODES * 256];   // layer input / layer output features
__device__ float g_xh  [NNODES * 512];   // x @ W (attention transform)
__device__ float g_lin [NNODES * 256];   // x @ lw (residual linear path)
__device__ float g_as  [NNODES * 4];     // per-node, per-head source score
__device__ float g_ad  [NNODES * 4];     // per-node, per-head dest score
__device__ int   g_off [NNODES + 1];     // CSR offsets (by dst)
__device__ int   g_cur [NNODES];         // counts, then write cursors
__device__ int   g_srcs[NEPLUS];         // CSR src list (by dst)
__device__ int   g_bsum[128];            // scan block sums
__device__ int   g_gcnt[NGRAPH];         // nodes per graph (pool)

__device__ __forceinline__ float lrelu(float x) { return x > 0.f ? x : 0.2f * x; }

// ---------------- embedding lookup ----------------
__global__ void k_embed(const int* __restrict__ xi, const float* __restrict__ emb) {
    int idx = blockIdx.x * blockDim.x + threadIdx.x;
    if (idx < NNODES * 128) {
        int n = idx >> 7, c = idx & 127;
        g_feat[n * 128 + c] = emb[xi[n] * 128 + c];
    }
}

// ---------------- CSR build (by dst, with self loops) ----------------
__global__ void k_cnt_init() {
    int i = blockIdx.x * blockDim.x + threadIdx.x;
    if (i < NNODES) g_cur[i] = 1;  // self loop
}
__global__ void k_hist(const int* __restrict__ edge) {
    int e = blockIdx.x * blockDim.x + threadIdx.x;
    if (e < NEDGES) atomicAdd(&g_cur[edge[NEDGES + e]], 1);
}
__global__ void k_scan1() {
    __shared__ int sh[256];
    int t = threadIdx.x, i = blockIdx.x * 256 + t;
    int v = (i < NNODES) ? g_cur[i] : 0;
    sh[t] = v;
    __syncthreads();
    for (int o = 1; o < 256; o <<= 1) {
        int x = (t >= o) ? sh[t - o] : 0;
        __syncthreads();
        sh[t] += x;
        __syncthreads();
    }
    if (i < NNODES) g_off[i] = sh[t] - v;   // exclusive within block
    if (t == 255) g_bsum[blockIdx.x] = sh[255];
}
__global__ void k_scan2(int nb) {
    if (threadIdx.x == 0) {
        int s = 0;
        for (int b = 0; b < nb; b++) { int v = g_bsum[b]; g_bsum[b] = s; s += v; }
    }
}
__global__ void k_scan3() {
    int i = blockIdx.x * 256 + threadIdx.x;
    if (i < NNODES) {
        int o = g_off[i] + g_bsum[i >> 8];
        g_off[i] = o;
        g_cur[i] = o;
    }
    if (i == 0) g_off[NNODES] = NEPLUS;
}
__global__ void k_scatter(const int* __restrict__ edge) {
    int e = blockIdx.x * blockDim.x + threadIdx.x;
    if (e < NEPLUS) {
        int s, d;
        if (e < NEDGES) { s = edge[e]; d = edge[NEDGES + e]; }
        else            { s = d = e - NEDGES; }
        int p = atomicAdd(&g_cur[d], 1);
        g_srcs[p] = s;
    }
}

// ---------------- SGEMM: C[M,Nc] = A[M,K] @ B[K,Nc]; Nc%64==0, K%16==0 ----------------
__global__ void sgemm(const float* __restrict__ A, const float* __restrict__ B,
                      float* __restrict__ C, int M, int K, int Nc) {
    __shared__ float As[16][68];  // padded, row stride 272B keeps 16B alignment
    __shared__ float Bs[16][64];
    int tid = threadIdx.x;
    int m0 = blockIdx.y * 64, n0 = blockIdx.x * 64;
    int tx = tid & 15, ty = tid >> 4;
    int ar = tid >> 2, ac = (tid & 3) * 4;   // A tile loader coords
    int br = tid >> 4, bc = (tid & 15) * 4;  // B tile loader coords
    float acc[4][4] = {};
    for (int kk = 0; kk < K; kk += 16) {
        float4 av = make_float4(0.f, 0.f, 0.f, 0.f);
        if (m0 + ar < M) av = *(const float4*)(A + (size_t)(m0 + ar) * K + kk + ac);
        As[ac + 0][ar] = av.x; As[ac + 1][ar] = av.y;
        As[ac + 2][ar] = av.z; As[ac + 3][ar] = av.w;
        float4 bv = *(const float4*)(B + (size_t)(kk + br) * Nc + n0 + bc);
        *(float4*)&Bs[br][bc] = bv;
        __syncthreads();
#pragma unroll
        for (int k = 0; k < 16; k++) {
            float4 a4 = *(const float4*)&As[k][ty * 4];
            float4 b4 = *(const float4*)&Bs[k][tx * 4];
            float a[4] = {a4.x, a4.y, a4.z, a4.w};
            float b[4] = {b4.x, b4.y, b4.z, b4.w};
#pragma unroll
            for (int i = 0; i < 4; i++)
#pragma unroll
                for (int j = 0; j < 4; j++) acc[i][j] += a[i] * b[j];
        }
        __syncthreads();
    }
#pragma unroll
    for (int i = 0; i < 4; i++) {
        int m = m0 + ty * 4 + i;
        if (m < M)
            *(float4*)(C + (size_t)m * Nc + n0 + tx * 4) =
                make_float4(acc[i][0], acc[i][1], acc[i][2], acc[i][3]);
    }
}

// ---------------- attention scores: a_s/a_d[n,h] = <xh[n,h,:], att[h,:]> ----------------
__global__ void k_att(const float* __restrict__ atts, const float* __restrict__ attd, int C) {
    int gt = blockIdx.x * blockDim.x + threadIdx.x;
    int w = gt >> 5, lane = gt & 31;
    if (w >= NNODES * 4) return;
    int n = w >> 2, h = w & 3;
    const float* xr = g_xh + (size_t)n * 4 * C + h * C;
    float ss = 0.f, sd = 0.f;
    for (int c = lane; c < C; c += 32) {
        float v = xr[c];
        ss += v * atts[h * C + c];
        sd += v * attd[h * C + c];
    }
    for (int o = 16; o; o >>= 1) {
        ss += __shfl_xor_sync(0xffffffffu, ss, o);
        sd += __shfl_xor_sync(0xffffffffu, sd, o);
    }
    if (lane == 0) { g_as[n * 4 + h] = ss; g_ad[n * 4 + h] = sd; }
}

// ---------------- GAT aggregation, concat heads (C=64, F=256). warp per node ----------------
__global__ void k_gat_concat(const float* __restrict__ bias, const float* __restrict__ lbias,
                             int relu_flag) {
    int gt = blockIdx.x * blockDim.x + threadIdx.x;
    int i = gt >> 5, lane = gt & 31;
    if (i >= NNODES) return;
    int beg = g_off[i], end = g_off[i + 1];
    float ad0 = g_ad[i * 4 + 0], ad1 = g_ad[i * 4 + 1];
    float ad2 = g_ad[i * 4 + 2], ad3 = g_ad[i * 4 + 3];
    float m0 = -1e30f, m1 = -1e30f, m2 = -1e30f, m3 = -1e30f;
    for (int e = beg + lane; e < end; e += 32) {
        int s = g_srcs[e];
        m0 = fmaxf(m0, lrelu(g_as[s * 4 + 0] + ad0));
        m1 = fmaxf(m1, lrelu(g_as[s * 4 + 1] + ad1));
        m2 = fmaxf(m2, lrelu(g_as[s * 4 + 2] + ad2));
        m3 = fmaxf(m3, lrelu(g_as[s * 4 + 3] + ad3));
    }
    for (int o = 16; o; o >>= 1) {
        m0 = fmaxf(m0, __shfl_xor_sync(0xffffffffu, m0, o));
        m1 = fmaxf(m1, __shfl_xor_sync(0xffffffffu, m1, o));
        m2 = fmaxf(m2, __shfl_xor_sync(0xffffffffu, m2, o));
        m3 = fmaxf(m3, __shfl_xor_sync(0xffffffffu, m3, o));
    }
    float z0 = 0.f, z1 = 0.f, z2 = 0.f, z3 = 0.f;
    for (int e = beg + lane; e < end; e += 32) {
        int s = g_srcs[e];
        z0 += __expf(lrelu(g_as[s * 4 + 0] + ad0) - m0);
        z1 += __expf(lrelu(g_as[s * 4 + 1] + ad1) - m1);
        z2 += __expf(lrelu(g_as[s * 4 + 2] + ad2) - m2);
        z3 += __expf(lrelu(g_as[s * 4 + 3] + ad3) - m3);
    }
    for (int o = 16; o; o >>= 1) {
        z0 += __shfl_xor_sync(0xffffffffu, z0, o);
        z1 += __shfl_xor_sync(0xffffffffu, z1, o);
        z2 += __shfl_xor_sync(0xffffffffu, z2, o);
        z3 += __shfl_xor_sync(0xffffffffu, z3, o);
    }
    float i0 = 1.f / (z0 + 1e-16f), i1 = 1.f / (z1 + 1e-16f);
    float i2 = 1.f / (z2 + 1e-16f), i3 = 1.f / (z3 + 1e-16f);
    float acc[8] = {0.f, 0.f, 0.f, 0.f, 0.f, 0.f, 0.f, 0.f};
    for (int e = beg; e < end; e++) {
        int s = g_srcs[e];
        float w0 = __expf(lrelu(g_as[s * 4 + 0] + ad0) - m0) * i0;
        float w1 = __expf(lrelu(g_as[s * 4 + 1] + ad1) - m1) * i1;
        float w2 = __expf(lrelu(g_as[s * 4 + 2] + ad2) - m2) * i2;
        float w3 = __expf(lrelu(g_as[s * 4 + 3] + ad3) - m3) * i3;
        const float* xr = g_xh + (size_t)s * 256;
        acc[0] += w0 * xr[lane +   0]; acc[1] += w0 * xr[lane +  32];
        acc[2] += w1 * xr[lane +  64]; acc[3] += w1 * xr[lane +  96];
        acc[4] += w2 * xr[lane + 128]; acc[5] += w2 * xr[lane + 160];
        acc[6] += w3 * xr[lane + 192]; acc[7] += w3 * xr[lane + 224];
    }
    const float* lr = g_lin + (size_t)i * 256;
    float* outp = g_feat + (size_t)i * 256;
#pragma unroll
    for (int k = 0; k < 8; k++) {
        int c = lane + 32 * k;
        float v = acc[k] + bias[c] + lr[c] + lbias[c];
        outp[c] = relu_flag ? fmaxf(v, 0.f) : v;
    }
}

// ---------------- GAT aggregation, mean over heads (C=128, F=512 -> 128) ----------------
__global__ void k_gat_mean(const float* __restrict__ bias, const float* __restrict__ lbias) {
    int gt = blockIdx.x * blockDim.x + threadIdx.x;
    int i = gt >> 5, lane = gt & 31;
    if (i >= NNODES) return;
    int beg = g_off[i], end = g_off[i + 1];
    float ad0 = g_ad[i * 4 + 0], ad1 = g_ad[i * 4 + 1];
    float ad2 = g_ad[i * 4 + 2], ad3 = g_ad[i * 4 + 3];
    float m0 = -1e30f, m1 = -1e30f, m2 = -1e30f, m3 = -1e30f;
    for (int e = beg + lane; e < end; e += 32) {
        int s = g_srcs[e];
        m0 = fmaxf(m0, lrelu(g_as[s * 4 + 0] + ad0));
        m1 = fmaxf(m1, lrelu(g_as[s * 4 + 1] + ad1));
        m2 = fmaxf(m2, lrelu(g_as[s * 4 + 2] + ad2));
        m3 = fmaxf(m3, lrelu(g_as[s * 4 + 3] + ad3));
    }
    for (int o = 16; o; o >>= 1) {
        m0 = fmaxf(m0, __shfl_xor_sync(0xffffffffu, m0, o));
        m1 = fmaxf(m1, __shfl_xor_sync(0xffffffffu, m1, o));
        m2 = fmaxf(m2, __shfl_xor_sync(0xffffffffu, m2, o));
        m3 = fmaxf(m3, __shfl_xor_sync(0xffffffffu, m3, o));
    }
    float z0 = 0.f, z1 = 0.f, z2 = 0.f, z3 = 0.f;
    for (int e = beg + lane; e < end; e += 32) {
        int s = g_srcs[e];
        z0 += __expf(lrelu(g_as[s * 4 + 0] + ad0) - m0);
        z1 += __expf(lrelu(g_as[s * 4 + 1] + ad1) - m1);
        z2 += __expf(lrelu(g_as[s * 4 + 2] + ad2) - m2);
        z3 += __expf(lrelu(g_as[s * 4 + 3] + ad3) - m3);
    }
    for (int o = 16; o; o >>= 1) {
        z0 += __shfl_xor_sync(0xffffffffu, z0, o);
        z1 += __shfl_xor_sync(0xffffffffu, z1, o);
        z2 += __shfl_xor_sync(0xffffffffu, z2, o);
        z3 += __shfl_xor_sync(0xffffffffu, z3, o);
    }
    float i0 = 1.f / (z0 + 1e-16f), i1 = 1.f / (z1 + 1e-16f);
    float i2 = 1.f / (z2 + 1e-16f), i3 = 1.f / (z3 + 1e-16f);
    float acc[4] = {0.f, 0.f, 0.f, 0.f};
    for (int e = beg; e < end; e++) {
        int s = g_srcs[e];
        float w0 = __expf(lrelu(g_as[s * 4 + 0] + ad0) - m0) * i0;
        float w1 = __expf(lrelu(g_as[s * 4 + 1] + ad1) - m1) * i1;
        float w2 = __expf(lrelu(g_as[s * 4 + 2] + ad2) - m2) * i2;
        float w3 = __expf(lrelu(g_as[s * 4 + 3] + ad3) - m3) * i3;
        const float* xr = g_xh + (size_t)s * 512;
#pragma unroll
        for (int k = 0; k < 4; k++) {
            int c = lane + 32 * k;
            acc[k] += w0 * xr[c] + w1 * xr[c + 128] + w2 * xr[c + 256] + w3 * xr[c + 384];
        }
    }
    const float* lr = g_lin + (size_t)i * 128;
    float* outp = g_feat + (size_t)i * 128;
#pragma unroll
    for (int k = 0; k < 4; k++) {
        int c = lane + 32 * k;
        outp[c] = 0.25f * acc[k] + bias[c] + lr[c] + lbias[c];
    }
}

// ---------------- global mean pool ----------------
__global__ void k_pool_init(float* out) {
    int i = blockIdx.x * blockDim.x + threadIdx.x;
    if (i < NGRAPH * 128) out[i] = 0.f;
    if (i < NGRAPH) g_gcnt[i] = 0;
}
__global__ void k_pool_cnt(const int* __restrict__ batch) {
    int n = blockIdx.x * blockDim.x + threadIdx.x;
    if (n < NNODES) atomicAdd(&g_gcnt[batch[n]], 1);
}
__global__ void k_pool_sum(const int* __restrict__ batch, float* out) {
    int idx = blockIdx.x * blockDim.x + threadIdx.x;
    if (idx < NNODES * 128) {
        int n = idx >> 7, c = idx & 127;
        atomicAdd(&out[batch[n] * 128 + c], g_feat[n * 128 + c]);
    }
}
__global__ void k_pool_div(float* out) {
    int i = blockIdx.x * blockDim.x + threadIdx.x;
    if (i < NGRAPH * 128) {
        float cnt = (float)g_gcnt[i >> 7];
        out[i] /= fmaxf(cnt, 1.f);
    }
}

// ---------------- host orchestration ----------------
struct Params {
    const float *emb;
    const float *W1, *as1, *ad1, *b1, *lw1, *lb1;
    const float *W2, *as2, *ad2, *b2, *lw2, *lb2;
    const float *W3, *as3, *ad3, *b3, *lw3, *lb3;
};

static void run_side(const int* x, const int* edge, const int* batch,
                     const Params& p, float* out) {
    float *feat, *xh, *lin;
    cudaGetSymbolAddress((void**)&feat, g_feat);
    cudaGetSymbolAddress((void**)&xh, g_xh);
    cudaGetSymbolAddress((void**)&lin, g_lin);

    const int TB = 256;
    k_embed<<<(NNODES * 128 + TB - 1) / TB, TB>>>(x, p.emb);

    // CSR by dst
    k_cnt_init<<<(NNODES + TB - 1) / TB, TB>>>();
    k_hist<<<(NEDGES + TB - 1) / TB, TB>>>(edge);
    k_scan1<<<SCAN_BLOCKS, 256>>>();
    k_scan2<<<1, 32>>>(SCAN_BLOCKS);
    k_scan3<<<SCAN_BLOCKS, 256>>>();
    k_scatter<<<(NEPLUS + TB - 1) / TB, TB>>>(edge);

    dim3 gN256(256 / 64, (NNODES + 63) / 64);
    dim3 gN512(512 / 64, (NNODES + 63) / 64);
    dim3 gN128(128 / 64, (NNODES + 63) / 64);
    int att_grid = (NNODES * 4 * 32 + TB - 1) / TB;
    int gat_grid = (NNODES * 32 + TB - 1) / TB;

    // Layer 1 (in 128 -> 256)
    sgemm<<<gN256, 256>>>(feat, p.W1, xh, NNODES, 128, 256);
    sgemm<<<gN256, 256>>>(feat, p.lw1, lin, NNODES, 128, 256);
    k_att<<<att_grid, TB>>>(p.as1, p.ad1, 64);
    k_gat_concat<<<gat_grid, TB>>>(p.b1, p.lb1, 1);

    // Layer 2 (256 -> 256)
    sgemm<<<gN256, 256>>>(feat, p.W2, xh, NNODES, 256, 256);
    sgemm<<<gN256, 256>>>(feat, p.lw2, lin, NNODES, 256, 256);
    k_att<<<att_grid, TB>>>(p.as2, p.ad2, 64);
    k_gat_concat<<<gat_grid, TB>>>(p.b2, p.lb2, 1);

    // Layer 3 (256 -> 128, mean over heads, no relu)
    sgemm<<<gN512, 256>>>(feat, p.W3, xh, NNODES, 256, 512);
    sgemm<<<gN128, 256>>>(feat, p.lw3, lin, NNODES, 256, 128);
    k_att<<<att_grid, TB>>>(p.as3, p.ad3, 128);
    k_gat_mean<<<gat_grid, TB>>>(p.b3, p.lb3);

    // Pool
    k_pool_init<<<(NGRAPH * 128 + TB - 1) / TB, TB>>>(out);
    k_pool_cnt<<<(NNODES + TB - 1) / TB, TB>>>(batch);
    k_pool_sum<<<(NNODES * 128 + TB - 1) / TB, TB>>>(batch, out);
    k_pool_div<<<(NGRAPH * 128 + TB - 1) / TB, TB>>>(out);
}

extern "C" void kernel_launch(void* const* d_in, const int* in_sizes, int n_in,
                              void* d_out, int out_size) {
    const int* x_l     = (const int*)d_in[0];
    const int* edge_l  = (const int*)d_in[1];
    const int* batch_l = (const int*)d_in[2];
    const int* x_r     = (const int*)d_in[3];
    const int* edge_r  = (const int*)d_in[4];
    const int* batch_r = (const int*)d_in[5];

    Params p;
    p.emb = (const float*)d_in[6];
    p.W1 = (const float*)d_in[7];  p.as1 = (const float*)d_in[8];  p.ad1 = (const float*)d_in[9];
    p.b1 = (const float*)d_in[10]; p.lw1 = (const float*)d_in[11]; p.lb1 = (const float*)d_in[12];
    p.W2 = (const float*)d_in[13]; p.as2 = (const float*)d_in[14]; p.ad2 = (const float*)d_in[15];
    p.b2 = (const float*)d_in[16]; p.lw2 = (const float*)d_in[17]; p.lb2 = (const float*)d_in[18];
    p.W3 = (const float*)d_in[19]; p.as3 = (const float*)d_in[20]; p.ad3 = (const float*)d_in[21];
    p.b3 = (const float*)d_in[22]; p.lw3 = (const float*)d_in[23]; p.lb3 = (const float*)d_in[24];

    float* out = (float*)d_out;
    run_side(x_l, edge_l, batch_l, p, out);
    run_side(x_r, edge_r, batch_r, p, out + NGRAPH * 128);
}

// round 2
// speedup vs baseline: 1.6320x; 1.6320x over previous
#include <cuda_runtime.h>

#define NNODES 20000
#define NEDGES 320000
#define NEPLUS 340000   // edges + self loops
#define NGRAPH 256
#define SCAN_BLOCKS 79  // ceil(20000/256)

// ---------------- scratch (device globals; no runtime alloc allowed) ----------------
__device__ float g_feat[NNODES * 256];   // layer input / layer output features
__device__ float g_xh  [NNODES * 512];   // x @ W (attention transform)
__device__ float g_lin [NNODES * 256];   // x @ lw (residual linear path)
__device__ float g_as  [NNODES * 4];     // per-node, per-head source score
__device__ float g_ad  [NNODES * 4];     // per-node, per-head dest score
__device__ int   g_off [NNODES + 1];     // CSR offsets (by dst)
__device__ int   g_cur [NNODES];         // counts, then write cursors
__device__ int   g_srcs[NEPLUS];         // CSR src list (by dst)
__device__ int   g_bsum[128];            // scan block sums
__device__ int   g_gcnt[NGRAPH];         // nodes per graph (pool)

__device__ __forceinline__ float lrelu(float x) { return x > 0.f ? x : 0.2f * x; }

__device__ __forceinline__ float tf32r(float x) {
    unsigned u;
    asm("cvt.rna.tf32.f32 %0, %1;" : "=r"(u) : "f"(x));
    return __uint_as_float(u);
}

// ---------------- embedding lookup ----------------
__global__ void k_embed(const int* __restrict__ xi, const float* __restrict__ emb) {
    int idx = blockIdx.x * blockDim.x + threadIdx.x;
    if (idx < NNODES * 128) {
        int n = idx >> 7, c = idx & 127;
        g_feat[n * 128 + c] = emb[xi[n] * 128 + c];
    }
}

// ---------------- CSR build (by dst, with self loops) ----------------
__global__ void k_cnt_init() {
    int i = blockIdx.x * blockDim.x + threadIdx.x;
    if (i < NNODES) g_cur[i] = 1;  // self loop
}
__global__ void k_hist(const int* __restrict__ edge) {
    int e = blockIdx.x * blockDim.x + threadIdx.x;
    if (e < NEDGES) atomicAdd(&g_cur[edge[NEDGES + e]], 1);
}
__global__ void k_scan1() {
    __shared__ int sh[256];
    int t = threadIdx.x, i = blockIdx.x * 256 + t;
    int v = (i < NNODES) ? g_cur[i] : 0;
    sh[t] = v;
    __syncthreads();
    for (int o = 1; o < 256; o <<= 1) {
        int x = (t >= o) ? sh[t - o] : 0;
        __syncthreads();
        sh[t] += x;
        __syncthreads();
    }
    if (i < NNODES) g_off[i] = sh[t] - v;   // exclusive within block
    if (t == 255) g_bsum[blockIdx.x] = sh[255];
}
__global__ void k_scan2(int nb) {
    if (threadIdx.x == 0) {
        int s = 0;
        for (int b = 0; b < nb; b++) { int v = g_bsum[b]; g_bsum[b] = s; s += v; }
    }
}
__global__ void k_scan3() {
    int i = blockIdx.x * 256 + threadIdx.x;
    if (i < NNODES) {
        int o = g_off[i] + g_bsum[i >> 8];
        g_off[i] = o;
        g_cur[i] = o;
    }
    if (i == 0) g_off[NNODES] = NEPLUS;
}
__global__ void k_scatter(const int* __restrict__ edge) {
    int e = blockIdx.x * blockDim.x + threadIdx.x;
    if (e < NEPLUS) {
        int s, d;
        if (e < NEDGES) { s = edge[e]; d = edge[NEDGES + e]; }
        else            { s = d = e - NEDGES; }
        int p = atomicAdd(&g_cur[d], 1);
        g_srcs[p] = s;
    }
}

// ---------------- tf32 tensor-core GEMM: C[M,N] = A[M,K] @ B[K,N] ----------------
// Block tile 128x128x32, 8 warps, warp tile 64x32 (m16n8k8 grid of 4x4).
// N % 128 == 0, K % 32 == 0 assumed (256/512/128 and 128/256 here).
__device__ __forceinline__ void mma_tf32(float* c, const float* a, const float* b) {
    asm volatile(
        "mma.sync.aligned.m16n8k8.row.col.f32.tf32.tf32.f32 "
        "{%0,%1,%2,%3},{%4,%5,%6,%7},{%8,%9},{%0,%1,%2,%3};"
        : "+f"(c[0]), "+f"(c[1]), "+f"(c[2]), "+f"(c[3])
        : "r"(__float_as_uint(a[0])), "r"(__float_as_uint(a[1])),
          "r"(__float_as_uint(a[2])), "r"(__float_as_uint(a[3])),
          "r"(__float_as_uint(b[0])), "r"(__float_as_uint(b[1])));
}

__global__ void gemm_tf32(const float* __restrict__ A, const float* __restrict__ B,
                          float* __restrict__ C, int M, int K, int N) {
    __shared__ float As[128][36];   // pad 4 -> fragment LDS conflict-free
    __shared__ float Bs[32][136];   // pad 8 -> fragment LDS conflict-free
    int tid = threadIdx.x;
    int warp = tid >> 5, lane = tid & 31;
    int m0 = blockIdx.y * 128, n0 = blockIdx.x * 128;
    int wm = (warp >> 2) * 64;     // warp M offset: 0 / 64
    int wn = (warp & 3) * 32;      // warp N offset: 0..96
    int gid = lane >> 2, tig = lane & 3;

    float c[4][4][4];
#pragma unroll
    for (int i = 0; i < 4; i++)
#pragma unroll
        for (int j = 0; j < 4; j++)
#pragma unroll
            for (int r = 0; r < 4; r++) c[i][j][r] = 0.f;

    for (int kk = 0; kk < K; kk += 32) {
        // A tile: 128 rows x 32 cols = 1024 float4
#pragma unroll
        for (int i = 0; i < 4; i++) {
            int j = tid + 256 * i;
            int row = j >> 3, cq = (j & 7) << 2;
            float4 v = make_float4(0.f, 0.f, 0.f, 0.f);
            if (m0 + row < M) v = *(const float4*)(A + (size_t)(m0 + row) * K + kk + cq);
            v.x = tf32r(v.x); v.y = tf32r(v.y); v.z = tf32r(v.z); v.w = tf32r(v.w);
            *(float4*)&As[row][cq] = v;
        }
        // B tile: 32 rows x 128 cols = 1024 float4
#pragma unroll
        for (int i = 0; i < 4; i++) {
            int j = tid + 256 * i;
            int k = j >> 5, nq = (j & 31) << 2;
            float4 v = *(const float4*)(B + (size_t)(kk + k) * N + n0 + nq);
            v.x = tf32r(v.x); v.y = tf32r(v.y); v.z = tf32r(v.z); v.w = tf32r(v.w);
            *(float4*)&Bs[k][nq] = v;
        }
        __syncthreads();
#pragma unroll
        for (int ks = 0; ks < 4; ks++) {
            int kb = ks * 8;
            float a[4][4], b[4][2];
#pragma unroll
            for (int mi = 0; mi < 4; mi++) {
                int r = wm + mi * 16 + gid;
                a[mi][0] = As[r][kb + tig];
                a[mi][1] = As[r + 8][kb + tig];
                a[mi][2] = As[r][kb + tig + 4];
                a[mi][3] = As[r + 8][kb + tig + 4];
            }
#pragma unroll
            for (int ni = 0; ni < 4; ni++) {
                int cn = wn + ni * 8 + gid;
                b[ni][0] = Bs[kb + tig][cn];
                b[ni][1] = Bs[kb + tig + 4][cn];
            }
#pragma unroll
            for (int mi = 0; mi < 4; mi++)
#pragma unroll
                for (int ni = 0; ni < 4; ni++) mma_tf32(c[mi][ni], a[mi], b[ni]);
        }
        __syncthreads();
    }
    // epilogue
#pragma unroll
    for (int mi = 0; mi < 4; mi++) {
#pragma unroll
        for (int ni = 0; ni < 4; ni++) {
            int r0 = m0 + wm + mi * 16 + gid;
            int cc = n0 + wn + ni * 8 + tig * 2;
            if (r0 < M)
                *(float2*)(C + (size_t)r0 * N + cc) = make_float2(c[mi][ni][0], c[mi][ni][1]);
            if (r0 + 8 < M)
                *(float2*)(C + (size_t)(r0 + 8) * N + cc) = make_float2(c[mi][ni][2], c[mi][ni][3]);
        }
    }
}

// ---------------- attention scores: a_s/a_d[n,h] = <xh[n,h,:], att[h,:]> ----------------
__global__ void k_att(const float* __restrict__ atts, const float* __restrict__ attd, int C) {
    int gt = blockIdx.x * blockDim.x + threadIdx.x;
    int w = gt >> 5, lane = gt & 31;
    if (w >= NNODES * 4) return;
    int n = w >> 2, h = w & 3;
    const float* xr = g_xh + (size_t)n * 4 * C + h * C;
    float ss = 0.f, sd = 0.f;
    for (int c = lane; c < C; c += 32) {
        float v = xr[c];
        ss += v * atts[h * C + c];
        sd += v * attd[h * C + c];
    }
    for (int o = 16; o; o >>= 1) {
        ss += __shfl_xor_sync(0xffffffffu, ss, o);
        sd += __shfl_xor_sync(0xffffffffu, sd, o);
    }
    if (lane == 0) { g_as[n * 4 + h] = ss; g_ad[n * 4 + h] = sd; }
}

// ---------------- GAT aggregation, concat heads (C=64, F=256). warp per node ----------------
__global__ void k_gat_concat(const float* __restrict__ bias, const float* __restrict__ lbias,
                             int relu_flag) {
    int gt = blockIdx.x * blockDim.x + threadIdx.x;
    int i = gt >> 5, lane = gt & 31;
    if (i >= NNODES) return;
    int beg = g_off[i], end = g_off[i + 1];
    float4 ad = *(const float4*)(g_as + 0, g_ad + (size_t)i * 4);  // dummy avoid
    ad = *(const float4*)(g_ad + (size_t)i * 4);
    float m0 = -1e30f, m1 = -1e30f, m2 = -1e30f, m3 = -1e30f;
    for (int e = beg + lane; e < end; e += 32) {
        int s = g_srcs[e];
        float4 as = *(const float4*)(g_as + (size_t)s * 4);
        m0 = fmaxf(m0, lrelu(as.x + ad.x));
        m1 = fmaxf(m1, lrelu(as.y + ad.y));
        m2 = fmaxf(m2, lrelu(as.z + ad.z));
        m3 = fmaxf(m3, lrelu(as.w + ad.w));
    }
    for (int o = 16; o; o >>= 1) {
        m0 = fmaxf(m0, __shfl_xor_sync(0xffffffffu, m0, o));
        m1 = fmaxf(m1, __shfl_xor_sync(0xffffffffu, m1, o));
        m2 = fmaxf(m2, __shfl_xor_sync(0xffffffffu, m2, o));
        m3 = fmaxf(m3, __shfl_xor_sync(0xffffffffu, m3, o));
    }
    float z0 = 0.f, z1 = 0.f, z2 = 0.f, z3 = 0.f;
    for (int e = beg + lane; e < end; e += 32) {
        int s = g_srcs[e];
        float4 as = *(const float4*)(g_as + (size_t)s * 4);
        z0 += __expf(lrelu(as.x + ad.x) - m0);
        z1 += __expf(lrelu(as.y + ad.y) - m1);
        z2 += __expf(lrelu(as.z + ad.z) - m2);
        z3 += __expf(lrelu(as.w + ad.w) - m3);
    }
    for (int o = 16; o; o >>= 1) {
        z0 += __shfl_xor_sync(0xffffffffu, z0, o);
        z1 += __shfl_xor_sync(0xffffffffu, z1, o);
        z2 += __shfl_xor_sync(0xffffffffu, z2, o);
        z3 += __shfl_xor_sync(0xffffffffu, z3, o);
    }
    float i0 = 1.f / (z0 + 1e-16f), i1 = 1.f / (z1 + 1e-16f);
    float i2 = 1.f / (z2 + 1e-16f), i3 = 1.f / (z3 + 1e-16f);
    float acc[8] = {0.f, 0.f, 0.f, 0.f, 0.f, 0.f, 0.f, 0.f};
    for (int e = beg; e < end; e++) {
        int s = g_srcs[e];
        float4 as = *(const float4*)(g_as + (size_t)s * 4);
        float w0 = __expf(lrelu(as.x + ad.x) - m0) * i0;
        float w1 = __expf(lrelu(as.y + ad.y) - m1) * i1;
        float w2 = __expf(lrelu(as.z + ad.z) - m2) * i2;
        float w3 = __expf(lrelu(as.w + ad.w) - m3) * i3;
        const float* xr = g_xh + (size_t)s * 256;
        acc[0] += w0 * xr[lane +   0]; acc[1] += w0 * xr[lane +  32];
        acc[2] += w1 * xr[lane +  64]; acc[3] += w1 * xr[lane +  96];
        acc[4] += w2 * xr[lane + 128]; acc[5] += w2 * xr[lane + 160];
        acc[6] += w3 * xr[lane + 192]; acc[7] += w3 * xr[lane + 224];
    }
    const float* lr = g_lin + (size_t)i * 256;
    float* outp = g_feat + (size_t)i * 256;
#pragma unroll
    for (int k = 0; k < 8; k++) {
        int c = lane + 32 * k;
        float v = acc[k] + bias[c] + lr[c] + lbias[c];
        outp[c] = relu_flag ? fmaxf(v, 0.f) : v;
    }
}

// ---------------- GAT aggregation, mean over heads (C=128, F=512 -> 128) ----------------
__global__ void k_gat_mean(const float* __restrict__ bias, const float* __restrict__ lbias) {
    int gt = blockIdx.x * blockDim.x + threadIdx.x;
    int i = gt >> 5, lane = gt & 31;
    if (i >= NNODES) return;
    int beg = g_off[i], end = g_off[i + 1];
    float4 ad = *(const float4*)(g_ad + (size_t)i * 4);
    float m0 = -1e30f, m1 = -1e30f, m2 = -1e30f, m3 = -1e30f;
    for (int e = beg + lane; e < end; e += 32) {
        int s = g_srcs[e];
        float4 as = *(const float4*)(g_as + (size_t)s * 4);
        m0 = fmaxf(m0, lrelu(as.x + ad.x));
        m1 = fmaxf(m1, lrelu(as.y + ad.y));
        m2 = fmaxf(m2, lrelu(as.z + ad.z));
        m3 = fmaxf(m3, lrelu(as.w + ad.w));
    }
    for (int o = 16; o; o >>= 1) {
        m0 = fmaxf(m0, __shfl_xor_sync(0xffffffffu, m0, o));
        m1 = fmaxf(m1, __shfl_xor_sync(0xffffffffu, m1, o));
        m2 = fmaxf(m2, __shfl_xor_sync(0xffffffffu, m2, o));
        m3 = fmaxf(m3, __shfl_xor_sync(0xffffffffu, m3, o));
    }
    float z0 = 0.f, z1 = 0.f, z2 = 0.f, z3 = 0.f;
    for (int e = beg + lane; e < end; e += 32) {
        int s = g_srcs[e];
        float4 as = *(const float4*)(g_as + (size_t)s * 4);
        z0 += __expf(lrelu(as.x + ad.x) - m0);
        z1 += __expf(lrelu(as.y + ad.y) - m1);
        z2 += __expf(lrelu(as.z + ad.z) - m2);
        z3 += __expf(lrelu(as.w + ad.w) - m3);
    }
    for (int o = 16; o; o >>= 1) {
        z0 += __shfl_xor_sync(0xffffffffu, z0, o);
        z1 += __shfl_xor_sync(0xffffffffu, z1, o);
        z2 += __shfl_xor_sync(0xffffffffu, z2, o);
        z3 += __shfl_xor_sync(0xffffffffu, z3, o);
    }
    float i0 = 1.f / (z0 + 1e-16f), i1 = 1.f / (z1 + 1e-16f);
    float i2 = 1.f / (z2 + 1e-16f), i3 = 1.f / (z3 + 1e-16f);
    float acc[4] = {0.f, 0.f, 0.f, 0.f};
    for (int e = beg; e < end; e++) {
        int s = g_srcs[e];
        float4 as = *(const float4*)(g_as + (size_t)s * 4);
        float w0 = __expf(lrelu(as.x + ad.x) - m0) * i0;
        float w1 = __expf(lrelu(as.y + ad.y) - m1) * i1;
        float w2 = __expf(lrelu(as.z + ad.z) - m2) * i2;
        float w3 = __expf(lrelu(as.w + ad.w) - m3) * i3;
        const float* xr = g_xh + (size_t)s * 512;
#pragma unroll
        for (int k = 0; k < 4; k++) {
            int c = lane + 32 * k;
            acc[k] += w0 * xr[c] + w1 * xr[c + 128] + w2 * xr[c + 256] + w3 * xr[c + 384];
        }
    }
    const float* lr = g_lin + (size_t)i * 128;
    float* outp = g_feat + (size_t)i * 128;
#pragma unroll
    for (int k = 0; k < 4; k++) {
        int c = lane + 32 * k;
        outp[c] = 0.25f * acc[k] + bias[c] + lr[c] + lbias[c];
    }
}

// ---------------- global mean pool ----------------
__global__ void k_pool_init(float* out) {
    int i = blockIdx.x * blockDim.x + threadIdx.x;
    if (i < NGRAPH * 128) out[i] = 0.f;
    if (i < NGRAPH) g_gcnt[i] = 0;
}
__global__ void k_pool_cnt(const int* __restrict__ batch) {
    int n = blockIdx.x * blockDim.x + threadIdx.x;
    if (n < NNODES) atomicAdd(&g_gcnt[batch[n]], 1);
}
__global__ void k_pool_sum(const int* __restrict__ batch, float* out) {
    int idx = blockIdx.x * blockDim.x + threadIdx.x;
    if (idx < NNODES * 128) {
        int n = idx >> 7, c = idx & 127;
        atomicAdd(&out[batch[n] * 128 + c], g_feat[n * 128 + c]);
    }
}
__global__ void k_pool_div(float* out) {
    int i = blockIdx.x * blockDim.x + threadIdx.x;
    if (i < NGRAPH * 128) {
        float cnt = (float)g_gcnt[i >> 7];
        out[i] /= fmaxf(cnt, 1.f);
    }
}

// ---------------- host orchestration ----------------
struct Params {
    const float *emb;
    const float *W1, *as1, *ad1, *b1, *lw1, *lb1;
    const float *W2, *as2, *ad2, *b2, *lw2, *lb2;
    const float *W3, *as3, *ad3, *b3, *lw3, *lb3;
};

static void run_side(const int* x, const int* edge, const int* batch,
                     const Params& p, float* out) {
    float *feat, *xh, *lin;
    cudaGetSymbolAddress((void**)&feat, g_feat);
    cudaGetSymbolAddress((void**)&xh, g_xh);
    cudaGetSymbolAddress((void**)&lin, g_lin);

    const int TB = 256;
    k_embed<<<(NNODES * 128 + TB - 1) / TB, TB>>>(x, p.emb);

    // CSR by dst
    k_cnt_init<<<(NNODES + TB - 1) / TB, TB>>>();
    k_hist<<<(NEDGES + TB - 1) / TB, TB>>>(edge);
    k_scan1<<<SCAN_BLOCKS, 256>>>();
    k_scan2<<<1, 32>>>(SCAN_BLOCKS);
    k_scan3<<<SCAN_BLOCKS, 256>>>();
    k_scatter<<<(NEPLUS + TB - 1) / TB, TB>>>(edge);

    const int MB = (NNODES + 127) / 128;
    dim3 gN256(256 / 128, MB);
    dim3 gN512(512 / 128, MB);
    dim3 gN128(128 / 128, MB);
    int att_grid = (NNODES * 4 * 32 + TB - 1) / TB;
    int gat_grid = (NNODES * 32 + TB - 1) / TB;

    // Layer 1 (in 128 -> 256)
    gemm_tf32<<<gN256, 256>>>(feat, p.W1, xh, NNODES, 128, 256);
    gemm_tf32<<<gN256, 256>>>(feat, p.lw1, lin, NNODES, 128, 256);
    k_att<<<att_grid, TB>>>(p.as1, p.ad1, 64);
    k_gat_concat<<<gat_grid, TB>>>(p.b1, p.lb1, 1);

    // Layer 2 (256 -> 256)
    gemm_tf32<<<gN256, 256>>>(feat, p.W2, xh, NNODES, 256, 256);
    gemm_tf32<<<gN256, 256>>>(feat, p.lw2, lin, NNODES, 256, 256);
    k_att<<<att_grid, TB>>>(p.as2, p.ad2, 64);
    k_gat_concat<<<gat_grid, TB>>>(p.b2, p.lb2, 1);

    // Layer 3 (256 -> 128, mean over heads, no relu)
    gemm_tf32<<<gN512, 256>>>(feat, p.W3, xh, NNODES, 256, 512);
    gemm_tf32<<<gN128, 256>>>(feat, p.lw3, lin, NNODES, 256, 128);
    k_att<<<att_grid, TB>>>(p.as3, p.ad3, 128);
    k_gat_mean<<<gat_grid, TB>>>(p.b3, p.lb3);

    // Pool
    k_pool_init<<<(NGRAPH * 128 + TB - 1) / TB, TB>>>(out);
    k_pool_cnt<<<(NNODES + TB - 1) / TB, TB>>>(batch);
    k_pool_sum<<<(NNODES * 128 + TB - 1) / TB, TB>>>(batch, out);
    k_pool_div<<<(NGRAPH * 128 + TB - 1) / TB, TB>>>(out);
}

extern "C" void kernel_launch(void* const* d_in, const int* in_sizes, int n_in,
                              void* d_out, int out_size) {
    const int* x_l     = (const int*)d_in[0];
    const int* edge_l  = (const int*)d_in[1];
    const int* batch_l = (const int*)d_in[2];
    const int* x_r     = (const int*)d_in[3];
    const int* edge_r  = (const int*)d_in[4];
    const int* batch_r = (const int*)d_in[5];

    Params p;
    p.emb = (const float*)d_in[6];
    p.W1 = (const float*)d_in[7];  p.as1 = (const float*)d_in[8];  p.ad1 = (const float*)d_in[9];
    p.b1 = (const float*)d_in[10]; p.lw1 = (const float*)d_in[11]; p.lb1 = (const float*)d_in[12];
    p.W2 = (const float*)d_in[13]; p.as2 = (const float*)d_in[14]; p.ad2 = (const float*)d_in[15];
    p.b2 = (const float*)d_in[16]; p.lw2 = (const float*)d_in[17]; p.lb2 = (const float*)d_in[18];
    p.W3 = (const float*)d_in[19]; p.as3 = (const float*)d_in[20]; p.ad3 = (const float*)d_in[21];
    p.b3 = (const float*)d_in[22]; p.lw3 = (const float*)d_in[23]; p.lb3 = (const float*)d_in[24];

    float* out = (float*)d_out;
    run_side(x_l, edge_l, batch_l, p, out);
    run_side(x_r, edge_r, batch_r, p, out + NGRAPH * 128);
}

// round 3
// speedup vs baseline: 1.8137x; 1.1114x over previous
#include <cuda_runtime.h>

#define NNODES 20000
#define NEDGES 320000
#define NEPLUS 340000   // edges + self loops
#define NGRAPH 256
#define SCAN_BLOCKS 79  // ceil(20000/256)

// ---------------- scratch (device globals; no runtime alloc allowed) ----------------
__device__ float g_feat[NNODES * 256];   // layer input / layer output features
__device__ float g_xh  [NNODES * 512];   // x @ W (attention transform)
__device__ float g_lin [NNODES * 256];   // x @ lw (residual linear path)
__device__ float g_as  [NNODES * 4];     // per-node, per-head source score
__device__ float g_ad  [NNODES * 4];     // per-node, per-head dest score
__device__ float g_exp [NEPLUS * 4];     // cached per-edge exp (softmax numerator)
__device__ int   g_off [NNODES + 1];     // CSR offsets (by dst)
__device__ int   g_cur [NNODES];         // counts, then write cursors
__device__ int   g_srcs[NEPLUS];         // CSR src list (by dst)
__device__ int   g_bsum[128];            // scan block sums
__device__ int   g_gcnt[NGRAPH];         // nodes per graph (pool)

__device__ __forceinline__ float lrelu(float x) { return x > 0.f ? x : 0.2f * x; }

__device__ __forceinline__ float tf32r(float x) {
    unsigned u;
    asm("cvt.rna.tf32.f32 %0, %1;" : "=r"(u) : "f"(x));
    return __uint_as_float(u);
}

// ---------------- embedding lookup + CSR count init (fused) ----------------
__global__ void k_embed(const int* __restrict__ xi, const float* __restrict__ emb) {
    int idx = blockIdx.x * blockDim.x + threadIdx.x;
    if (idx < NNODES) g_cur[idx] = 1;  // self loop
    if (idx < NNODES * 128) {
        int n = idx >> 7, c = idx & 127;
        g_feat[n * 128 + c] = emb[xi[n] * 128 + c];
    }
}

// ---------------- CSR build (by dst, with self loops) ----------------
__global__ void k_hist(const int* __restrict__ edge) {
    int e = blockIdx.x * blockDim.x + threadIdx.x;
    if (e < NEDGES) atomicAdd(&g_cur[edge[NEDGES + e]], 1);
}
__global__ void k_scan1() {
    __shared__ int sh[256];
    int t = threadIdx.x, i = blockIdx.x * 256 + t;
    int v = (i < NNODES) ? g_cur[i] : 0;
    sh[t] = v;
    __syncthreads();
    for (int o = 1; o < 256; o <<= 1) {
        int x = (t >= o) ? sh[t - o] : 0;
        __syncthreads();
        sh[t] += x;
        __syncthreads();
    }
    if (i < NNODES) g_off[i] = sh[t] - v;   // exclusive within block
    if (t == 255) g_bsum[blockIdx.x] = sh[255];
}
__global__ void k_scan2(int nb) {
    if (threadIdx.x == 0) {
        int s = 0;
        for (int b = 0; b < nb; b++) { int v = g_bsum[b]; g_bsum[b] = s; s += v; }
    }
}
__global__ void k_scan3() {
    int i = blockIdx.x * 256 + threadIdx.x;
    if (i < NNODES) {
        int o = g_off[i] + g_bsum[i >> 8];
        g_off[i] = o;
        g_cur[i] = o;
    }
    if (i == 0) g_off[NNODES] = NEPLUS;
}
__global__ void k_scatter(const int* __restrict__ edge) {
    int e = blockIdx.x * blockDim.x + threadIdx.x;
    if (e < NEPLUS) {
        int s, d;
        if (e < NEDGES) { s = edge[e]; d = edge[NEDGES + e]; }
        else            { s = d = e - NEDGES; }
        int p = atomicAdd(&g_cur[d], 1);
        g_srcs[p] = s;
    }
}

// ---------------- tf32 tensor-core GEMM, dual output, reg-prefetch pipeline ---------
// Computes C1[M,N1] = A@B1 and C2[M,N2] = A@B2 in one launch (grid.x spans both).
// Block tile 128x128x32, 8 warps, warp tile 64x32. N1,N2 % 128 == 0, K % 32 == 0.
__device__ __forceinline__ void mma_tf32(float* c, const float* a, const float* b) {
    asm volatile(
        "mma.sync.aligned.m16n8k8.row.col.f32.tf32.tf32.f32 "
        "{%0,%1,%2,%3},{%4,%5,%6,%7},{%8,%9},{%0,%1,%2,%3};"
        : "+f"(c[0]), "+f"(c[1]), "+f"(c[2]), "+f"(c[3])
        : "r"(__float_as_uint(a[0])), "r"(__float_as_uint(a[1])),
          "r"(__float_as_uint(a[2])), "r"(__float_as_uint(a[3])),
          "r"(__float_as_uint(b[0])), "r"(__float_as_uint(b[1])));
}

__global__ __launch_bounds__(256) void gemm_dual(
    const float* __restrict__ A,
    const float* __restrict__ B1, float* __restrict__ C1, int N1,
    const float* __restrict__ B2, float* __restrict__ C2, int N2,
    int M, int K) {
    __shared__ float As[128][36];   // pad 4 -> fragment LDS conflict-free
    __shared__ float Bs[32][136];   // pad 8 -> fragment LDS conflict-free

    int t1 = N1 >> 7;
    const float* B; float* C; int N, n0;
    if ((int)blockIdx.x < t1) { B = B1; C = C1; N = N1; n0 = blockIdx.x << 7; }
    else { B = B2; C = C2; N = N2; n0 = (blockIdx.x - t1) << 7; }

    int tid = threadIdx.x;
    int warp = tid >> 5, lane = tid & 31;
    int m0 = blockIdx.y * 128;
    int wm = (warp >> 2) * 64;
    int wn = (warp & 3) * 32;
    int gid = lane >> 2, tig = lane & 3;

    // loader coords
    int arow = tid >> 3, acq = (tid & 7) << 2;    // A: 128 rows x 32 cols, +row stride 32/iter? (4 iters via +32 rows)
    int bk = tid >> 5, bnq = (tid & 31) << 2;     // B: 32 rows x 128 cols (4 iters via +8 rows)

    float c[4][4][4];
#pragma unroll
    for (int i = 0; i < 4; i++)
#pragma unroll
        for (int j = 0; j < 4; j++)
#pragma unroll
            for (int r = 0; r < 4; r++) c[i][j][r] = 0.f;

    float4 pa[4], pb[4];
    // prefetch k-tile 0
#pragma unroll
    for (int i = 0; i < 4; i++) {
        int row = arow + 32 * i;
        pa[i] = make_float4(0.f, 0.f, 0.f, 0.f);
        if (m0 + row < M) pa[i] = *(const float4*)(A + (size_t)(m0 + row) * K + acq);
        pb[i] = *(const float4*)(B + (size_t)(bk + 8 * i) * N + n0 + bnq);
    }

    for (int kk = 0; kk < K; kk += 32) {
        // store current prefetch to smem (with tf32 rounding)
#pragma unroll
        for (int i = 0; i < 4; i++) {
            int row = arow + 32 * i;
            float4 v = pa[i];
            v.x = tf32r(v.x); v.y = tf32r(v.y); v.z = tf32r(v.z); v.w = tf32r(v.w);
            *(float4*)&As[row][acq] = v;
            float4 w = pb[i];
            w.x = tf32r(w.x); w.y = tf32r(w.y); w.z = tf32r(w.z); w.w = tf32r(w.w);
            *(float4*)&Bs[bk + 8 * i][bnq] = w;
        }
        __syncthreads();
        // prefetch next k-tile while computing
        if (kk + 32 < K) {
            int kn = kk + 32;
#pragma unroll
            for (int i = 0; i < 4; i++) {
                int row = arow + 32 * i;
                pa[i] = make_float4(0.f, 0.f, 0.f, 0.f);
                if (m0 + row < M) pa[i] = *(const float4*)(A + (size_t)(m0 + row) * K + kn + acq);
                pb[i] = *(const float4*)(B + (size_t)(kn + bk + 8 * i) * N + n0 + bnq);
            }
        }
#pragma unroll
        for (int ks = 0; ks < 4; ks++) {
            int kb = ks * 8;
            float a[4][4], b[4][2];
#pragma unroll
            for (int mi = 0; mi < 4; mi++) {
                int r = wm + mi * 16 + gid;
                a[mi][0] = As[r][kb + tig];
                a[mi][1] = As[r + 8][kb + tig];
                a[mi][2] = As[r][kb + tig + 4];
                a[mi][3] = As[r + 8][kb + tig + 4];
            }
#pragma unroll
            for (int ni = 0; ni < 4; ni++) {
                int cn = wn + ni * 8 + gid;
                b[ni][0] = Bs[kb + tig][cn];
                b[ni][1] = Bs[kb + tig + 4][cn];
            }
#pragma unroll
            for (int mi = 0; mi < 4; mi++)
#pragma unroll
                for (int ni = 0; ni < 4; ni++) mma_tf32(c[mi][ni], a[mi], b[ni]);
        }
        __syncthreads();
    }
    // epilogue
#pragma unroll
    for (int mi = 0; mi < 4; mi++) {
#pragma unroll
        for (int ni = 0; ni < 4; ni++) {
            int r0 = m0 + wm + mi * 16 + gid;
            int cc = n0 + wn + ni * 8 + tig * 2;
            if (r0 < M)
                *(float2*)(C + (size_t)r0 * N + cc) = make_float2(c[mi][ni][0], c[mi][ni][1]);
            if (r0 + 8 < M)
                *(float2*)(C + (size_t)(r0 + 8) * N + cc) = make_float2(c[mi][ni][2], c[mi][ni][3]);
        }
    }
}

// ---------------- attention scores: a_s/a_d[n,h] = <xh[n,h,:], att[h,:]> ----------------
__global__ void k_att(const float* __restrict__ atts, const float* __restrict__ attd, int C) {
    int gt = blockIdx.x * blockDim.x + threadIdx.x;
    int w = gt >> 5, lane = gt & 31;
    if (w >= NNODES * 4) return;
    int n = w >> 2, h = w & 3;
    const float* xr = g_xh + (size_t)n * 4 * C + h * C;
    float ss = 0.f, sd = 0.f;
    for (int c = lane; c < C; c += 32) {
        float v = xr[c];
        ss += v * atts[h * C + c];
        sd += v * attd[h * C + c];
    }
    for (int o = 16; o; o >>= 1) {
        ss += __shfl_xor_sync(0xffffffffu, ss, o);
        sd += __shfl_xor_sync(0xffffffffu, sd, o);
    }
    if (lane == 0) { g_as[n * 4 + h] = ss; g_ad[n * 4 + h] = sd; }
}

// ---------------- GAT aggregation, concat heads (C=64, F=256). warp per node ----------------
__global__ void k_gat_concat(const float* __restrict__ bias, const float* __restrict__ lbias,
                             int relu_flag) {
    int gt = blockIdx.x * blockDim.x + threadIdx.x;
    int i = gt >> 5, lane = gt & 31;
    if (i >= NNODES) return;
    int beg = g_off[i], end = g_off[i + 1];
    float4 ad = *(const float4*)(g_ad + (size_t)i * 4);
    float m0 = -1e30f, m1 = -1e30f, m2 = -1e30f, m3 = -1e30f;
    for (int e = beg + lane; e < end; e += 32) {
        int s = g_srcs[e];
        float4 as = *(const float4*)(g_as + (size_t)s * 4);
        m0 = fmaxf(m0, lrelu(as.x + ad.x));
        m1 = fmaxf(m1, lrelu(as.y + ad.y));
        m2 = fmaxf(m2, lrelu(as.z + ad.z));
        m3 = fmaxf(m3, lrelu(as.w + ad.w));
    }
    for (int o = 16; o; o >>= 1) {
        m0 = fmaxf(m0, __shfl_xor_sync(0xffffffffu, m0, o));
        m1 = fmaxf(m1, __shfl_xor_sync(0xffffffffu, m1, o));
        m2 = fmaxf(m2, __shfl_xor_sync(0xffffffffu, m2, o));
        m3 = fmaxf(m3, __shfl_xor_sync(0xffffffffu, m3, o));
    }
    float z0 = 0.f, z1 = 0.f, z2 = 0.f, z3 = 0.f;
    for (int e = beg + lane; e < end; e += 32) {
        int s = g_srcs[e];
        float4 as = *(const float4*)(g_as + (size_t)s * 4);
        float e0 = __expf(lrelu(as.x + ad.x) - m0);
        float e1 = __expf(lrelu(as.y + ad.y) - m1);
        float e2 = __expf(lrelu(as.z + ad.z) - m2);
        float e3 = __expf(lrelu(as.w + ad.w) - m3);
        *(float4*)(g_exp + (size_t)e * 4) = make_float4(e0, e1, e2, e3);
        z0 += e0; z1 += e1; z2 += e2; z3 += e3;
    }
    for (int o = 16; o; o >>= 1) {
        z0 += __shfl_xor_sync(0xffffffffu, z0, o);
        z1 += __shfl_xor_sync(0xffffffffu, z1, o);
        z2 += __shfl_xor_sync(0xffffffffu, z2, o);
        z3 += __shfl_xor_sync(0xffffffffu, z3, o);
    }
    float i0 = 1.f / (z0 + 1e-16f), i1 = 1.f / (z1 + 1e-16f);
    float i2 = 1.f / (z2 + 1e-16f), i3 = 1.f / (z3 + 1e-16f);
    int h = lane >> 3;                       // head owned by this lane (8 lanes/head)
    float myinv = (h == 0) ? i0 : (h == 1) ? i1 : (h == 2) ? i2 : i3;
    int col = lane * 8;                      // 8 consecutive cols per lane
    float4 a0 = make_float4(0.f, 0.f, 0.f, 0.f), a1 = a0;
    for (int e = beg; e < end; e++) {
        int s = g_srcs[e];
        float w = g_exp[(size_t)e * 4 + h] * myinv;
        const float4* xr = (const float4*)(g_xh + (size_t)s * 256 + col);
        float4 v0 = xr[0], v1 = xr[1];
        a0.x += w * v0.x; a0.y += w * v0.y; a0.z += w * v0.z; a0.w += w * v0.w;
        a1.x += w * v1.x; a1.y += w * v1.y; a1.z += w * v1.z; a1.w += w * v1.w;
    }
    float4 lr0 = *(const float4*)(g_lin + (size_t)i * 256 + col);
    float4 lr1 = *(const float4*)(g_lin + (size_t)i * 256 + col + 4);
    float4 b0 = *(const float4*)(bias + col);
    float4 b1 = *(const float4*)(bias + col + 4);
    float4 lb0 = *(const float4*)(lbias + col);
    float4 lb1 = *(const float4*)(lbias + col + 4);
    float4 o0, o1;
    o0.x = a0.x + b0.x + lr0.x + lb0.x; o0.y = a0.y + b0.y + lr0.y + lb0.y;
    o0.z = a0.z + b0.z + lr0.z + lb0.z; o0.w = a0.w + b0.w + lr0.w + lb0.w;
    o1.x = a1.x + b1.x + lr1.x + lb1.x; o1.y = a1.y + b1.y + lr1.y + lb1.y;
    o1.z = a1.z + b1.z + lr1.z + lb1.z; o1.w = a1.w + b1.w + lr1.w + lb1.w;
    if (relu_flag) {
        o0.x = fmaxf(o0.x, 0.f); o0.y = fmaxf(o0.y, 0.f);
        o0.z = fmaxf(o0.z, 0.f); o0.w = fmaxf(o0.w, 0.f);
        o1.x = fmaxf(o1.x, 0.f); o1.y = fmaxf(o1.y, 0.f);
        o1.z = fmaxf(o1.z, 0.f); o1.w = fmaxf(o1.w, 0.f);
    }
    *(float4*)(g_feat + (size_t)i * 256 + col) = o0;
    *(float4*)(g_feat + (size_t)i * 256 + col + 4) = o1;
}

// ---------------- GAT aggregation, mean over heads (C=128, F=512 -> 128) ----------------
__global__ void k_gat_mean(const float* __restrict__ bias, const float* __restrict__ lbias) {
    int gt = blockIdx.x * blockDim.x + threadIdx.x;
    int i = gt >> 5, lane = gt & 31;
    if (i >= NNODES) return;
    int beg = g_off[i], end = g_off[i + 1];
    float4 ad = *(const float4*)(g_ad + (size_t)i * 4);
    float m0 = -1e30f, m1 = -1e30f, m2 = -1e30f, m3 = -1e30f;
    for (int e = beg + lane; e < end; e += 32) {
        int s = g_srcs[e];
        float4 as = *(const float4*)(g_as + (size_t)s * 4);
        m0 = fmaxf(m0, lrelu(as.x + ad.x));
        m1 = fmaxf(m1, lrelu(as.y + ad.y));
        m2 = fmaxf(m2, lrelu(as.z + ad.z));
        m3 = fmaxf(m3, lrelu(as.w + ad.w));
    }
    for (int o = 16; o; o >>= 1) {
        m0 = fmaxf(m0, __shfl_xor_sync(0xffffffffu, m0, o));
        m1 = fmaxf(m1, __shfl_xor_sync(0xffffffffu, m1, o));
        m2 = fmaxf(m2, __shfl_xor_sync(0xffffffffu, m2, o));
        m3 = fmaxf(m3, __shfl_xor_sync(0xffffffffu, m3, o));
    }
    float z0 = 0.f, z1 = 0.f, z2 = 0.f, z3 = 0.f;
    for (int e = beg + lane; e < end; e += 32) {
        int s = g_srcs[e];
        float4 as = *(const float4*)(g_as + (size_t)s * 4);
        float e0 = __expf(lrelu(as.x + ad.x) - m0);
        float e1 = __expf(lrelu(as.y + ad.y) - m1);
        float e2 = __expf(lrelu(as.z + ad.z) - m2);
        float e3 = __expf(lrelu(as.w + ad.w) - m3);
        *(float4*)(g_exp + (size_t)e * 4) = make_float4(e0, e1, e2, e3);
        z0 += e0; z1 += e1; z2 += e2; z3 += e3;
    }
    for (int o = 16; o; o >>= 1) {
        z0 += __shfl_xor_sync(0xffffffffu, z0, o);
        z1 += __shfl_xor_sync(0xffffffffu, z1, o);
        z2 += __shfl_xor_sync(0xffffffffu, z2, o);
        z3 += __shfl_xor_sync(0xffffffffu, z3, o);
    }
    float i0 = 1.f / (z0 + 1e-16f), i1 = 1.f / (z1 + 1e-16f);
    float i2 = 1.f / (z2 + 1e-16f), i3 = 1.f / (z3 + 1e-16f);
    int h = lane >> 3;
    float myinv = (h == 0) ? i0 : (h == 1) ? i1 : (h == 2) ? i2 : i3;
    int col = lane * 16;                     // cols [lane*16, lane*16+16) of 512
    float4 acc[4];
#pragma unroll
    for (int j = 0; j < 4; j++) acc[j] = make_float4(0.f, 0.f, 0.f, 0.f);
    for (int e = beg; e < end; e++) {
        int s = g_srcs[e];
        float w = g_exp[(size_t)e * 4 + h] * myinv;
        const float4* xr = (const float4*)(g_xh + (size_t)s * 512 + col);
#pragma unroll
        for (int j = 0; j < 4; j++) {
            float4 v = xr[j];
            acc[j].x += w * v.x; acc[j].y += w * v.y;
            acc[j].z += w * v.z; acc[j].w += w * v.w;
        }
    }
    // reduce across the 4 heads: lanes {b, b+8, b+16, b+24} hold same inner cols
#pragma unroll
    for (int mask = 8; mask <= 16; mask <<= 1) {
#pragma unroll
        for (int j = 0; j < 4; j++) {
            acc[j].x += __shfl_xor_sync(0xffffffffu, acc[j].x, mask);
            acc[j].y += __shfl_xor_sync(0xffffffffu, acc[j].y, mask);
            acc[j].z += __shfl_xor_sync(0xffffffffu, acc[j].z, mask);
            acc[j].w += __shfl_xor_sync(0xffffffffu, acc[j].w, mask);
        }
    }
    if (lane < 8) {
        int c0 = lane * 16;
#pragma unroll
        for (int j = 0; j < 4; j++) {
            int c = c0 + j * 4;
            float4 lr = *(const float4*)(g_lin + (size_t)i * 128 + c);
            float4 bb = *(const float4*)(bias + c);
            float4 lb = *(const float4*)(lbias + c);
            float4 o;
            o.x = 0.25f * acc[j].x + bb.x + lr.x + lb.x;
            o.y = 0.25f * acc[j].y + bb.y + lr.y + lb.y;
            o.z = 0.25f * acc[j].z + bb.z + lr.z + lb.z;
            o.w = 0.25f * acc[j].w + bb.w + lr.w + lb.w;
            *(float4*)(g_feat + (size_t)i * 128 + c) = o;
        }
    }
}

// ---------------- global mean pool ----------------
__global__ void k_pool_init(float* out) {
    int i = blockIdx.x * blockDim.x + threadIdx.x;
    if (i < NGRAPH * 128) out[i] = 0.f;
    if (i < NGRAPH) g_gcnt[i] = 0;
}
__global__ void k_pool_sum(const int* __restrict__ batch, float* out) {
    int idx = blockIdx.x * blockDim.x + threadIdx.x;
    if (idx < NNODES * 128) {
        int n = idx >> 7, c = idx & 127;
        int b = batch[n];
        if (c == 0) atomicAdd(&g_gcnt[b], 1);
        atomicAdd(&out[b * 128 + c], g_feat[n * 128 + c]);
    }
}
__global__ void k_pool_div(float* out) {
    int i = blockIdx.x * blockDim.x + threadIdx.x;
    if (i < NGRAPH * 128) {
        float cnt = (float)g_gcnt[i >> 7];
        out[i] /= fmaxf(cnt, 1.f);
    }
}

// ---------------- host orchestration ----------------
struct Params {
    const float *emb;
    const float *W1, *as1, *ad1, *b1, *lw1, *lb1;
    const float *W2, *as2, *ad2, *b2, *lw2, *lb2;
    const float *W3, *as3, *ad3, *b3, *lw3, *lb3;
};

static void run_side(const int* x, const int* edge, const int* batch,
                     const Params& p, float* out) {
    float *feat, *xh, *lin;
    cudaGetSymbolAddress((void**)&feat, g_feat);
    cudaGetSymbolAddress((void**)&xh, g_xh);
    cudaGetSymbolAddress((void**)&lin, g_lin);

    const int TB = 256;
    k_embed<<<(NNODES * 128 + TB - 1) / TB, TB>>>(x, p.emb);

    // CSR by dst
    k_hist<<<(NEDGES + TB - 1) / TB, TB>>>(edge);
    k_scan1<<<SCAN_BLOCKS, 256>>>();
    k_scan2<<<1, 32>>>(SCAN_BLOCKS);
    k_scan3<<<SCAN_BLOCKS, 256>>>();
    k_scatter<<<(NEPLUS + TB - 1) / TB, TB>>>(edge);

    const int MB = (NNODES + 127) / 128;
    int att_grid = (NNODES * 4 * 32 + TB - 1) / TB;
    int gat_grid = (NNODES * 32 + TB - 1) / TB;

    // Layer 1 (in 128 -> 256): xh = feat@W1, lin = feat@lw1 (one launch)
    gemm_dual<<<dim3(4, MB), 256>>>(feat, p.W1, xh, 256, p.lw1, lin, 256, NNODES, 128);
    k_att<<<att_grid, TB>>>(p.as1, p.ad1, 64);
    k_gat_concat<<<gat_grid, TB>>>(p.b1, p.lb1, 1);

    // Layer 2 (256 -> 256)
    gemm_dual<<<dim3(4, MB), 256>>>(feat, p.W2, xh, 256, p.lw2, lin, 256, NNODES, 256);
    k_att<<<att_grid, TB>>>(p.as2, p.ad2, 64);
    k_gat_concat<<<gat_grid, TB>>>(p.b2, p.lb2, 1);

    // Layer 3 (256 -> 512 xh / 128 lin, mean over heads, no relu)
    gemm_dual<<<dim3(5, MB), 256>>>(feat, p.W3, xh, 512, p.lw3, lin, 128, NNODES, 256);
    k_att<<<att_grid, TB>>>(p.as3, p.ad3, 128);
    k_gat_mean<<<gat_grid, TB>>>(p.b3, p.lb3);

    // Pool
    k_pool_init<<<(NGRAPH * 128 + TB - 1) / TB, TB>>>(out);
    k_pool_sum<<<(NNODES * 128 + TB - 1) / TB, TB>>>(batch, out);
    k_pool_div<<<(NGRAPH * 128 + TB - 1) / TB, TB>>>(out);
}

extern "C" void kernel_launch(void* const* d_in, const int* in_sizes, int n_in,
                              void* d_out, int out_size) {
    const int* x_l     = (const int*)d_in[0];
    const int* edge_l  = (const int*)d_in[1];
    const int* batch_l = (const int*)d_in[2];
    const int* x_r     = (const int*)d_in[3];
    const int* edge_r  = (const int*)d_in[4];
    const int* batch_r = (const int*)d_in[5];

    Params p;
    p.emb = (const float*)d_in[6];
    p.W1 = (const float*)d_in[7];  p.as1 = (const float*)d_in[8];  p.ad1 = (const float*)d_in[9];
    p.b1 = (const float*)d_in[10]; p.lw1 = (const float*)d_in[11]; p.lb1 = (const float*)d_in[12];
    p.W2 = (const float*)d_in[13]; p.as2 = (const float*)d_in[14]; p.ad2 = (const float*)d_in[15];
    p.b2 = (const float*)d_in[16]; p.lw2 = (const float*)d_in[17]; p.lb2 = (const float*)d_in[18];
    p.W3 = (const float*)d_in[19]; p.as3 = (const float*)d_in[20]; p.ad3 = (const float*)d_in[21];
    p.b3 = (const float*)d_in[22]; p.lw3 = (const float*)d_in[23]; p.lb3 = (const float*)d_in[24];

    float* out = (float*)d_out;
    run_side(x_l, edge_l, batch_l, p, out);
    run_side(x_r, edge_r, batch_r, p, out + NGRAPH * 128);
}

// round 5
// speedup vs baseline: 2.0649x; 1.1385x over previous
#include <cuda_runtime.h>
#include <cstdint>

#define NNODES 20000
#define NEDGES 320000
#define NEPLUS 340000   // edges + self loops
#define NGRAPH 256
#define VOCAB  128

// ---------------- scratch (device globals; no runtime alloc allowed) ----------------
__device__ float g_feat[2][NNODES * 256];
__device__ float g_xh  [2][NNODES * 512];
__device__ float g_lin [2][NNODES * 256];
__device__ float g_as  [2][NNODES * 4];
__device__ float g_ad  [2][NNODES * 4];
__device__ float g_exp [2][NEPLUS * 4];
__device__ int   g_off [2][NNODES + 1];
__device__ int   g_cur [2][NNODES];
__device__ int   g_srcs[2][NEPLUS];
__device__ int   g_gcnt[2][NGRAPH];
__device__ float g_tab [VOCAB * 512];    // [emb@W1 | emb@lw1] per vocab id
__device__ float g_tatt[VOCAB * 8];      // layer-1 a_s[4], a_d[4] per vocab id

__device__ __forceinline__ float lrelu(float x) { return x > 0.f ? x : 0.2f * x; }

__device__ __forceinline__ unsigned tf32u(float x) {
    unsigned u;
    asm("cvt.rna.tf32.f32 %0, %1;" : "=r"(u) : "f"(x));
    return u;
}

__device__ __forceinline__ uint32_t sptr(const void* p) {
    return (uint32_t)__cvta_generic_to_shared(p);
}
#define CPA(dst, src, sz) \
    asm volatile("cp.async.cg.shared.global [%0], [%1], 16, %2;" :: "r"(dst), "l"(src), "r"(sz))
#define CP_COMMIT() asm volatile("cp.async.commit_group;" ::: "memory")
#define CP_WAIT1()  asm volatile("cp.async.wait_group 1;" ::: "memory")
#define CP_WAIT0()  asm volatile("cp.async.wait_group 0;" ::: "memory")

// ---------------- layer-1 precompute: tables over the 128-entry vocab ----------------
__global__ void k_pre(const float* __restrict__ emb, const float* __restrict__ W1,
                      const float* __restrict__ lw1, const float* __restrict__ as1,
                      const float* __restrict__ ad1) {
    __shared__ float er[128];
    __shared__ float sAs[4], sAd[4];
    int v = blockIdx.x, t = threadIdx.x;  // 256 threads
    if (t < 128) er[t] = emb[v * 128 + t];
    if (t < 4) { sAs[t] = 0.f; sAd[t] = 0.f; }
    __syncthreads();
    float acc0 = 0.f, acc1 = 0.f;
    for (int k = 0; k < 128; k++) {
        float e = er[k];
        acc0 += e * W1[k * 256 + t];
        acc1 += e * lw1[k * 256 + t];
    }
    g_tab[v * 512 + t] = acc0;
    g_tab[v * 512 + 256 + t] = acc1;
    int h = t >> 6, c = t & 63;
    atomicAdd(&sAs[h], acc0 * as1[h * 64 + c]);
    atomicAdd(&sAd[h], acc0 * ad1[h * 64 + c]);
    __syncthreads();
    if (t < 4) { g_tatt[v * 8 + t] = sAs[t]; g_tatt[v * 8 + 4 + t] = sAd[t]; }
}

// ---------------- init: CSR counts (self loop), pool accumulators, out ----------------
__global__ void k_init(float* out) {
    int i = blockIdx.x * blockDim.x + threadIdx.x;
    if (i < 2 * NNODES) g_cur[i / NNODES][i % NNODES] = 1;
    if (i < 2 * NGRAPH * 128) out[i] = 0.f;
    if (i < 2 * NGRAPH) g_gcnt[i >> 8][i & 255] = 0;
}

// ---------------- CSR build ----------------
__global__ void k_hist(const int* __restrict__ el, const int* __restrict__ er) {
    int side = blockIdx.z;
    const int* edge = side ? er : el;
    int e = blockIdx.x * blockDim.x + threadIdx.x;
    if (e < NEDGES) atomicAdd(&g_cur[side][edge[NEDGES + e]], 1);
}

// single-block scan per side (1024 threads x 20 items)
__global__ void k_scan() {
    int side = blockIdx.x;
    __shared__ int wsum[32];
    int t = threadIdx.x, lane = t & 31, w = t >> 5;
    const int IT = 20;
    int base = t * IT;
    int vals[IT];
    int s = 0;
#pragma unroll
    for (int j = 0; j < IT; j++) {
        int i = base + j;
        vals[j] = (i < NNODES) ? g_cur[side][i] : 0;
        s += vals[j];
    }
    int ps = s;
    for (int o = 1; o < 32; o <<= 1) {
        int v = __shfl_up_sync(0xffffffffu, ps, o);
        if (lane >= o) ps += v;
    }
    if (lane == 31) wsum[w] = ps;
    __syncthreads();
    if (w == 0) {
        int v = wsum[lane];
        for (int o = 1; o < 32; o <<= 1) {
            int u = __shfl_up_sync(0xffffffffu, v, o);
            if (lane >= o) v += u;
        }
        wsum[lane] = v;
    }
    __syncthreads();
    int run = ps - s + (w > 0 ? wsum[w - 1] : 0);
#pragma unroll
    for (int j = 0; j < IT; j++) {
        int i = base + j;
        if (i < NNODES) {
            g_off[side][i] = run;
            g_cur[side][i] = run;
            run += vals[j];
        }
    }
    if (t == 1023) g_off[side][NNODES] = NEPLUS;
}

__global__ void k_scatter(const int* __restrict__ el, const int* __restrict__ er) {
    int side = blockIdx.z;
    const int* edge = side ? er : el;
    int e = blockIdx.x * blockDim.x + threadIdx.x;
    if (e < NEPLUS) {
        int s, d;
        if (e < NEDGES) { s = edge[e]; d = edge[NEDGES + e]; }
        else            { s = d = e - NEDGES; }
        int p = atomicAdd(&g_cur[side][d], 1);
        g_srcs[side][p] = s;
    }
}

// ---------------- layer-1 "GEMM" via table gather ----------------
__global__ void k_l1gather(const int* __restrict__ xl, const int* __restrict__ xr) {
    int side = blockIdx.z;
    const int* xi = side ? xr : xl;
    int idx = blockIdx.x * blockDim.x + threadIdx.x;
    if (idx >= NNODES * 128) return;
    int n = idx >> 7, q = idx & 127;
    int v = xi[n];
    float4 val = *(const float4*)(g_tab + v * 512 + q * 4);
    if (q < 64) *(float4*)(&g_xh[side][n * 256 + q * 4]) = val;
    else        *(float4*)(&g_lin[side][n * 256 + (q - 64) * 4]) = val;
    if (q == 0) {
        *(float4*)(&g_as[side][n * 4]) = *(const float4*)(g_tatt + v * 8);
        *(float4*)(&g_ad[side][n * 4]) = *(const float4*)(g_tatt + v * 8 + 4);
    }
}

// ---------------- tf32 tensor-core GEMM, dual output, cp.async double-buffer --------
// RNA tf32 rounding applied on fragments AFTER smem load (cp.async path carries raw fp32).
__device__ __forceinline__ void mma_tf32(float* c, const unsigned* a, const unsigned* b) {
    asm volatile(
        "mma.sync.aligned.m16n8k8.row.col.f32.tf32.tf32.f32 "
        "{%0,%1,%2,%3},{%4,%5,%6,%7},{%8,%9},{%0,%1,%2,%3};"
        : "+f"(c[0]), "+f"(c[1]), "+f"(c[2]), "+f"(c[3])
        : "r"(a[0]), "r"(a[1]), "r"(a[2]), "r"(a[3]),
          "r"(b[0]), "r"(b[1]));
}

// dynamic smem: As[2][128][36] then Bs[2][32][136]
#define AS_STRIDE 36
#define BS_STRIDE 136
#define GEMM_SMEM ((2 * 128 * AS_STRIDE + 2 * 32 * BS_STRIDE) * 4)

__global__ __launch_bounds__(256) void gemm_dual(
    const float* __restrict__ Abase, long sA,
    const float* __restrict__ B1, float* __restrict__ C1base, long sC1, int N1,
    const float* __restrict__ B2, float* __restrict__ C2base, long sC2, int N2,
    int M, int K) {
    extern __shared__ float smem[];
    float (*As)[128][AS_STRIDE] = (float (*)[128][AS_STRIDE])smem;
    float (*Bs)[32][BS_STRIDE] = (float (*)[32][BS_STRIDE])(smem + 2 * 128 * AS_STRIDE);

    int side = blockIdx.z;
    const float* A = Abase + (size_t)side * sA;
    int t1 = N1 >> 7;
    const float* B; float* C; int N, n0;
    if ((int)blockIdx.x < t1) { B = B1; C = C1base + (size_t)side * sC1; N = N1; n0 = blockIdx.x << 7; }
    else { B = B2; C = C2base + (size_t)side * sC2; N = N2; n0 = (blockIdx.x - t1) << 7; }

    int tid = threadIdx.x;
    int warp = tid >> 5, lane = tid & 31;
    int m0 = blockIdx.y * 128;
    int wm = (warp >> 2) * 64;
    int wn = (warp & 3) * 32;
    int gid = lane >> 2, tig = lane & 3;

    int arow = tid >> 3, acq = (tid & 7) << 2;
    int bk = tid >> 5, bnq = (tid & 31) << 2;

    float c[4][4][4];
#pragma unroll
    for (int i = 0; i < 4; i++)
#pragma unroll
        for (int j = 0; j < 4; j++)
#pragma unroll
            for (int r = 0; r < 4; r++) c[i][j][r] = 0.f;

    auto load_tile = [&](int s, int kk) {
#pragma unroll
        for (int i = 0; i < 4; i++) {
            int row = arow + 32 * i;
            const float* asrc = A + (size_t)(m0 + row) * K + kk + acq;
            int sz = (m0 + row < M) ? 16 : 0;
            if (!sz) asrc = A;
            CPA(sptr(&As[s][row][acq]), asrc, sz);
            const float* bsrc = B + (size_t)(kk + bk + 8 * i) * N + n0 + bnq;
            CPA(sptr(&Bs[s][bk + 8 * i][bnq]), bsrc, 16);
        }
        CP_COMMIT();
    };

    auto compute = [&](int s) {
#pragma unroll
        for (int ks = 0; ks < 4; ks++) {
            int kb = ks * 8;
            unsigned a[4][4], b[4][2];
#pragma unroll
            for (int mi = 0; mi < 4; mi++) {
                int r = wm + mi * 16 + gid;
                a[mi][0] = tf32u(As[s][r][kb + tig]);
                a[mi][1] = tf32u(As[s][r + 8][kb + tig]);
                a[mi][2] = tf32u(As[s][r][kb + tig + 4]);
                a[mi][3] = tf32u(As[s][r + 8][kb + tig + 4]);
            }
#pragma unroll
            for (int ni = 0; ni < 4; ni++) {
                int cn = wn + ni * 8 + gid;
                b[ni][0] = tf32u(Bs[s][kb + tig][cn]);
                b[ni][1] = tf32u(Bs[s][kb + tig + 4][cn]);
            }
#pragma unroll
            for (int mi = 0; mi < 4; mi++)
#pragma unroll
                for (int ni = 0; ni < 4; ni++) mma_tf32(c[mi][ni], a[mi], b[ni]);
        }
    };

    int KT = K >> 5;
    load_tile(0, 0);
    for (int kt = 0; kt < KT; kt++) {
        if (kt + 1 < KT) {
            load_tile((kt + 1) & 1, (kt + 1) << 5);
            CP_WAIT1();
        } else {
            CP_WAIT0();
        }
        __syncthreads();
        compute(kt & 1);
        __syncthreads();
    }
#pragma unroll
    for (int mi = 0; mi < 4; mi++) {
#pragma unroll
        for (int ni = 0; ni < 4; ni++) {
            int r0 = m0 + wm + mi * 16 + gid;
            int cc = n0 + wn + ni * 8 + tig * 2;
            if (r0 < M)
                *(float2*)(C + (size_t)r0 * N + cc) = make_float2(c[mi][ni][0], c[mi][ni][1]);
            if (r0 + 8 < M)
                *(float2*)(C + (size_t)(r0 + 8) * N + cc) = make_float2(c[mi][ni][2], c[mi][ni][3]);
        }
    }
}

// ---------------- attention scores ----------------
__global__ void k_att(const float* __restrict__ atts, const float* __restrict__ attd, int C) {
    int side = blockIdx.z;
    int gt = blockIdx.x * blockDim.x + threadIdx.x;
    int w = gt >> 5, lane = gt & 31;
    if (w >= NNODES * 4) return;
    int n = w >> 2, h = w & 3;
    const float* xr = g_xh[side] + (size_t)n * 4 * C + h * C;
    float ss = 0.f, sd = 0.f;
    for (int c = lane; c < C; c += 32) {
        float v = xr[c];
        ss += v * atts[h * C + c];
        sd += v * attd[h * C + c];
    }
    for (int o = 16; o; o >>= 1) {
        ss += __shfl_xor_sync(0xffffffffu, ss, o);
        sd += __shfl_xor_sync(0xffffffffu, sd, o);
    }
    if (lane == 0) { g_as[side][n * 4 + h] = ss; g_ad[side][n * 4 + h] = sd; }
}

// ---------------- GAT aggregation, concat heads (C=64, F=256). warp per node --------
__global__ void k_gat_concat(const float* __restrict__ bias, const float* __restrict__ lbias,
                             int relu_flag) {
    int side = blockIdx.z;
    int gt = blockIdx.x * blockDim.x + threadIdx.x;
    int i = gt >> 5, lane = gt & 31;
    if (i >= NNODES) return;
    int beg = g_off[side][i], end = g_off[side][i + 1];
    float4 ad = *(const float4*)(&g_ad[side][(size_t)i * 4]);
    float m0 = -1e30f, m1 = -1e30f, m2 = -1e30f, m3 = -1e30f;
    for (int e = beg + lane; e < end; e += 32) {
        int s = g_srcs[side][e];
        float4 as = *(const float4*)(&g_as[side][(size_t)s * 4]);
        m0 = fmaxf(m0, lrelu(as.x + ad.x));
        m1 = fmaxf(m1, lrelu(as.y + ad.y));
        m2 = fmaxf(m2, lrelu(as.z + ad.z));
        m3 = fmaxf(m3, lrelu(as.w + ad.w));
    }
    for (int o = 16; o; o >>= 1) {
        m0 = fmaxf(m0, __shfl_xor_sync(0xffffffffu, m0, o));
        m1 = fmaxf(m1, __shfl_xor_sync(0xffffffffu, m1, o));
        m2 = fmaxf(m2, __shfl_xor_sync(0xffffffffu, m2, o));
        m3 = fmaxf(m3, __shfl_xor_sync(0xffffffffu, m3, o));
    }
    float z0 = 0.f, z1 = 0.f, z2 = 0.f, z3 = 0.f;
    for (int e = beg + lane; e < end; e += 32) {
        int s = g_srcs[side][e];
        float4 as = *(const float4*)(&g_as[side][(size_t)s * 4]);
        float e0 = __expf(lrelu(as.x + ad.x) - m0);
        float e1 = __expf(lrelu(as.y + ad.y) - m1);
        float e2 = __expf(lrelu(as.z + ad.z) - m2);
        float e3 = __expf(lrelu(as.w + ad.w) - m3);
        *(float4*)(&g_exp[side][(size_t)e * 4]) = make_float4(e0, e1, e2, e3);
        z0 += e0; z1 += e1; z2 += e2; z3 += e3;
    }
    for (int o = 16; o; o >>= 1) {
        z0 += __shfl_xor_sync(0xffffffffu, z0, o);
        z1 += __shfl_xor_sync(0xffffffffu, z1, o);
        z2 += __shfl_xor_sync(0xffffffffu, z2, o);
        z3 += __shfl_xor_sync(0xffffffffu, z3, o);
    }
    float i0 = 1.f / (z0 + 1e-16f), i1 = 1.f / (z1 + 1e-16f);
    float i2 = 1.f / (z2 + 1e-16f), i3 = 1.f / (z3 + 1e-16f);
    int h = lane >> 3;
    float myinv = (h == 0) ? i0 : (h == 1) ? i1 : (h == 2) ? i2 : i3;
    int col = lane * 8;
    float4 a0 = make_float4(0.f, 0.f, 0.f, 0.f), a1 = a0;
    for (int e = beg; e < end; e++) {
        int s = g_srcs[side][e];
        float w = g_exp[side][(size_t)e * 4 + h] * myinv;
        const float4* xr = (const float4*)(g_xh[side] + (size_t)s * 256 + col);
        float4 v0 = xr[0], v1 = xr[1];
        a0.x += w * v0.x; a0.y += w * v0.y; a0.z += w * v0.z; a0.w += w * v0.w;
        a1.x += w * v1.x; a1.y += w * v1.y; a1.z += w * v1.z; a1.w += w * v1.w;
    }
    float4 lr0 = *(const float4*)(g_lin[side] + (size_t)i * 256 + col);
    float4 lr1 = *(const float4*)(g_lin[side] + (size_t)i * 256 + col + 4);
    float4 b0 = *(const float4*)(bias + col);
    float4 b1 = *(const float4*)(bias + col + 4);
    float4 lb0 = *(const float4*)(lbias + col);
    float4 lb1 = *(const float4*)(lbias + col + 4);
    float4 o0, o1;
    o0.x = a0.x + b0.x + lr0.x + lb0.x; o0.y = a0.y + b0.y + lr0.y + lb0.y;
    o0.z = a0.z + b0.z + lr0.z + lb0.z; o0.w = a0.w + b0.w + lr0.w + lb0.w;
    o1.x = a1.x + b1.x + lr1.x + lb1.x; o1.y = a1.y + b1.y + lr1.y + lb1.y;
    o1.z = a1.z + b1.z + lr1.z + lb1.z; o1.w = a1.w + b1.w + lr1.w + lb1.w;
    if (relu_flag) {
        o0.x = fmaxf(o0.x, 0.f); o0.y = fmaxf(o0.y, 0.f);
        o0.z = fmaxf(o0.z, 0.f); o0.w = fmaxf(o0.w, 0.f);
        o1.x = fmaxf(o1.x, 0.f); o1.y = fmaxf(o1.y, 0.f);
        o1.z = fmaxf(o1.z, 0.f); o1.w = fmaxf(o1.w, 0.f);
    }
    *(float4*)(g_feat[side] + (size_t)i * 256 + col) = o0;
    *(float4*)(g_feat[side] + (size_t)i * 256 + col + 4) = o1;
}

// ---------------- GAT aggregation, mean over heads (C=128, F=512 -> 128) ------------
__global__ void k_gat_mean(const float* __restrict__ bias, const float* __restrict__ lbias) {
    int side = blockIdx.z;
    int gt = blockIdx.x * blockDim.x + threadIdx.x;
    int i = gt >> 5, lane = gt & 31;
    if (i >= NNODES) return;
    int beg = g_off[side][i], end = g_off[side][i + 1];
    float4 ad = *(const float4*)(&g_ad[side][(size_t)i * 4]);
    float m0 = -1e30f, m1 = -1e30f, m2 = -1e30f, m3 = -1e30f;
    for (int e = beg + lane; e < end; e += 32) {
        int s = g_srcs[side][e];
        float4 as = *(const float4*)(&g_as[side][(size_t)s * 4]);
        m0 = fmaxf(m0, lrelu(as.x + ad.x));
        m1 = fmaxf(m1, lrelu(as.y + ad.y));
        m2 = fmaxf(m2, lrelu(as.z + ad.z));
        m3 = fmaxf(m3, lrelu(as.w + ad.w));
    }
    for (int o = 16; o; o >>= 1) {
        m0 = fmaxf(m0, __shfl_xor_sync(0xffffffffu, m0, o));
        m1 = fmaxf(m1, __shfl_xor_sync(0xffffffffu, m1, o));
        m2 = fmaxf(m2, __shfl_xor_sync(0xffffffffu, m2, o));
        m3 = fmaxf(m3, __shfl_xor_sync(0xffffffffu, m3, o));
    }
    float z0 = 0.f, z1 = 0.f, z2 = 0.f, z3 = 0.f;
    for (int e = beg + lane; e < end; e += 32) {
        int s = g_srcs[side][e];
        float4 as = *(const float4*)(&g_as[side][(size_t)s * 4]);
        float e0 = __expf(lrelu(as.x + ad.x) - m0);
        float e1 = __expf(lrelu(as.y + ad.y) - m1);
        float e2 = __expf(lrelu(as.z + ad.z) - m2);
        float e3 = __expf(lrelu(as.w + ad.w) - m3);
        *(float4*)(&g_exp[side][(size_t)e * 4]) = make_float4(e0, e1, e2, e3);
        z0 += e0; z1 += e1; z2 += e2; z3 += e3;
    }
    for (int o = 16; o; o >>= 1) {
        z0 += __shfl_xor_sync(0xffffffffu, z0, o);
        z1 += __shfl_xor_sync(0xffffffffu, z1, o);
        z2 += __shfl_xor_sync(0xffffffffu, z2, o);
        z3 += __shfl_xor_sync(0xffffffffu, z3, o);
    }
    float i0 = 1.f / (z0 + 1e-16f), i1 = 1.f / (z1 + 1e-16f);
    float i2 = 1.f / (z2 + 1e-16f), i3 = 1.f / (z3 + 1e-16f);
    int h = lane >> 3;
    float myinv = (h == 0) ? i0 : (h == 1) ? i1 : (h == 2) ? i2 : i3;
    int col = lane * 16;
    float4 acc[4];
#pragma unroll
    for (int j = 0; j < 4; j++) acc[j] = make_float4(0.f, 0.f, 0.f, 0.f);
    for (int e = beg; e < end; e++) {
        int s = g_srcs[side][e];
        float w = g_exp[side][(size_t)e * 4 + h] * myinv;
        const float4* xr = (const float4*)(g_xh[side] + (size_t)s * 512 + col);
#pragma unroll
        for (int j = 0; j < 4; j++) {
            float4 v = xr[j];
            acc[j].x += w * v.x; acc[j].y += w * v.y;
            acc[j].z += w * v.z; acc[j].w += w * v.w;
        }
    }
#pragma unroll
    for (int mask = 8; mask <= 16; mask <<= 1) {
#pragma unroll
        for (int j = 0; j < 4; j++) {
            acc[j].x += __shfl_xor_sync(0xffffffffu, acc[j].x, mask);
            acc[j].y += __shfl_xor_sync(0xffffffffu, acc[j].y, mask);
            acc[j].z += __shfl_xor_sync(0xffffffffu, acc[j].z, mask);
            acc[j].w += __shfl_xor_sync(0xffffffffu, acc[j].w, mask);
        }
    }
    if (lane < 8) {
        int c0 = lane * 16;
#pragma unroll
        for (int j = 0; j < 4; j++) {
            int c = c0 + j * 4;
            float4 lr = *(const float4*)(g_lin[side] + (size_t)i * 128 + c);
            float4 bb = *(const float4*)(bias + c);
            float4 lb = *(const float4*)(lbias + c);
            float4 o;
            o.x = 0.25f * acc[j].x + bb.x + lr.x + lb.x;
            o.y = 0.25f * acc[j].y + bb.y + lr.y + lb.y;
            o.z = 0.25f * acc[j].z + bb.z + lr.z + lb.z;
            o.w = 0.25f * acc[j].w + bb.w + lr.w + lb.w;
            *(float4*)(g_feat[side] + (size_t)i * 128 + c) = o;
        }
    }
}

// ---------------- global mean pool ----------------
__global__ void k_pool_sum(const int* __restrict__ bl, const int* __restrict__ br, float* out) {
    int side = blockIdx.z;
    const int* batch = side ? br : bl;
    int idx = blockIdx.x * blockDim.x + threadIdx.x;
    if (idx < NNODES * 128) {
        int n = idx >> 7, c = idx & 127;
        int b = batch[n];
        if (c == 0) atomicAdd(&g_gcnt[side][b], 1);
        atomicAdd(&out[side * NGRAPH * 128 + b * 128 + c], g_feat[side][n * 128 + c]);
    }
}
__global__ void k_pool_div(float* out) {
    int i = blockIdx.x * blockDim.x + threadIdx.x;
    if (i < 2 * NGRAPH * 128) {
        int side = i >> 15;  // 32768 per side
        float cnt = (float)g_gcnt[side][(i >> 7) & 255];
        out[i] /= fmaxf(cnt, 1.f);
    }
}

// ---------------- host orchestration ----------------
extern "C" void kernel_launch(void* const* d_in, const int* in_sizes, int n_in,
                              void* d_out, int out_size) {
    const int* x_l     = (const int*)d_in[0];
    const int* edge_l  = (const int*)d_in[1];
    const int* batch_l = (const int*)d_in[2];
    const int* x_r     = (const int*)d_in[3];
    const int* edge_r  = (const int*)d_in[4];
    const int* batch_r = (const int*)d_in[5];
    const float* emb = (const float*)d_in[6];
    const float* W1  = (const float*)d_in[7];  const float* as1 = (const float*)d_in[8];
    const float* ad1 = (const float*)d_in[9];  const float* b1  = (const float*)d_in[10];
    const float* lw1 = (const float*)d_in[11]; const float* lb1 = (const float*)d_in[12];
    const float* W2  = (const float*)d_in[13]; const float* as2 = (const float*)d_in[14];
    const float* ad2 = (const float*)d_in[15]; const float* b2  = (const float*)d_in[16];
    const float* lw2 = (const float*)d_in[17]; const float* lb2 = (const float*)d_in[18];
    const float* W3  = (const float*)d_in[19]; const float* as3 = (const float*)d_in[20];
    const float* ad3 = (const float*)d_in[21]; const float* b3  = (const float*)d_in[22];
    const float* lw3 = (const float*)d_in[23]; const float* lb3 = (const float*)d_in[24];
    float* out = (float*)d_out;

    float *feat, *xh, *lin;
    cudaGetSymbolAddress((void**)&feat, g_feat);
    cudaGetSymbolAddress((void**)&xh, g_xh);
    cudaGetSymbolAddress((void**)&lin, g_lin);

    cudaFuncSetAttribute(gemm_dual, cudaFuncAttributeMaxDynamicSharedMemorySize, GEMM_SMEM);

    const int TB = 256;
    const long sFeat = (long)NNODES * 256, sXh = (long)NNODES * 512, sLin = (long)NNODES * 256;
    const int MB = (NNODES + 127) / 128;
    int att_grid = (NNODES * 4 * 32 + TB - 1) / TB;
    int gat_grid = (NNODES * 32 + TB - 1) / TB;

    // precompute + init + CSR (both sides fused)
    k_pre<<<VOCAB, 256>>>(emb, W1, lw1, as1, ad1);
    k_init<<<(2 * NGRAPH * 128 + TB - 1) / TB, TB>>>(out);
    k_hist<<<dim3((NEDGES + TB - 1) / TB, 1, 2), TB>>>(edge_l, edge_r);
    k_scan<<<2, 1024>>>();
    k_scatter<<<dim3((NEPLUS + TB - 1) / TB, 1, 2), TB>>>(edge_l, edge_r);

    // Layer 1: table gather replaces GEMM + att
    k_l1gather<<<dim3((NNODES * 128 + TB - 1) / TB, 1, 2), TB>>>(x_l, x_r);
    k_gat_concat<<<dim3(gat_grid, 1, 2), TB>>>(b1, lb1, 1);

    // Layer 2 (256 -> 256)
    gemm_dual<<<dim3(4, MB, 2), 256, GEMM_SMEM>>>(feat, sFeat, W2, xh, sXh, 256,
                                                  lw2, lin, sLin, 256, NNODES, 256);
    k_att<<<dim3(att_grid, 1, 2), TB>>>(as2, ad2, 64);
    k_gat_concat<<<dim3(gat_grid, 1, 2), TB>>>(b2, lb2, 1);

    // Layer 3 (256 -> 512 xh / 128 lin)
    gemm_dual<<<dim3(5, MB, 2), 256, GEMM_SMEM>>>(feat, sFeat, W3, xh, sXh, 512,
                                                  lw3, lin, sLin, 128, NNODES, 256);
    k_att<<<dim3(att_grid, 1, 2), TB>>>(as3, ad3, 128);
    k_gat_mean<<<dim3(gat_grid, 1, 2), TB>>>(b3, lb3);

    // Pool
    k_pool_sum<<<dim3((NNODES * 128 + TB - 1) / TB, 1, 2), TB>>>(batch_l, batch_r, out);
    k_pool_div<<<(2 * NGRAPH * 128 + TB - 1) / TB, TB>>>(out);
}

// round 6
// speedup vs baseline: 2.7753x; 1.3440x over previous
#include <cuda_runtime.h>
#include <cuda_fp16.h>
#include <cstdint>

#define NNODES 20000
#define NEDGES 320000
#define NEPLUS 340000   // edges + self loops
#define NGRAPH 256
#define VOCAB  128

// ---------------- scratch (device globals; no runtime alloc allowed) ----------------
__device__ float  g_feat[2][NNODES * 256];
__device__ __half g_xh  [2][NNODES * 512];   // fp16 message features
__device__ float  g_lin [2][NNODES * 256];
__device__ float  g_as  [2][NNODES * 4];
__device__ float  g_ad  [2][NNODES * 4];
__device__ float  g_exp [2][NEPLUS * 4];
__device__ int    g_off [2][NNODES + 1];
__device__ int    g_cur [2][NNODES];
__device__ int    g_srcs[2][NEPLUS];
__device__ int    g_gcnt[2][NGRAPH];
__device__ float  g_tab [VOCAB * 512];    // [emb@W1 | emb@lw1] per vocab id
__device__ float  g_tatt[VOCAB * 8];      // layer-1 a_s[4], a_d[4] per vocab id

__device__ __forceinline__ float lrelu(float x) { return x > 0.f ? x : 0.2f * x; }

__device__ __forceinline__ unsigned tf32u(float x) {
    unsigned u;
    asm("cvt.rna.tf32.f32 %0, %1;" : "=r"(u) : "f"(x));
    return u;
}

__device__ __forceinline__ uint32_t sptr(const void* p) {
    return (uint32_t)__cvta_generic_to_shared(p);
}
#define CPA(dst, src, sz) \
    asm volatile("cp.async.cg.shared.global [%0], [%1], 16, %2;" :: "r"(dst), "l"(src), "r"(sz))
#define CP_COMMIT() asm volatile("cp.async.commit_group;" ::: "memory")
#define CP_WAIT1()  asm volatile("cp.async.wait_group 1;" ::: "memory")
#define CP_WAIT0()  asm volatile("cp.async.wait_group 0;" ::: "memory")

// ---------------- layer-1 precompute: tables over the 128-entry vocab ----------------
__global__ void k_pre(const float* __restrict__ emb, const float* __restrict__ W1,
                      const float* __restrict__ lw1, const float* __restrict__ as1,
                      const float* __restrict__ ad1) {
    __shared__ float er[128];
    __shared__ float sAs[4], sAd[4];
    int v = blockIdx.x, t = threadIdx.x;  // 256 threads
    if (t < 128) er[t] = emb[v * 128 + t];
    if (t < 4) { sAs[t] = 0.f; sAd[t] = 0.f; }
    __syncthreads();
    float acc0 = 0.f, acc1 = 0.f;
    for (int k = 0; k < 128; k++) {
        float e = er[k];
        acc0 += e * W1[k * 256 + t];
        acc1 += e * lw1[k * 256 + t];
    }
    g_tab[v * 512 + t] = acc0;
    g_tab[v * 512 + 256 + t] = acc1;
    int h = t >> 6, c = t & 63;
    atomicAdd(&sAs[h], acc0 * as1[h * 64 + c]);
    atomicAdd(&sAd[h], acc0 * ad1[h * 64 + c]);
    __syncthreads();
    if (t < 4) { g_tatt[v * 8 + t] = sAs[t]; g_tatt[v * 8 + 4 + t] = sAd[t]; }
}

// ---------------- init: CSR counts (self loop), pool accumulators, out ----------------
__global__ void k_init(float* out) {
    int i = blockIdx.x * blockDim.x + threadIdx.x;
    if (i < 2 * NNODES) g_cur[i / NNODES][i % NNODES] = 1;
    if (i < 2 * NGRAPH * 128) out[i] = 0.f;
    if (i < 2 * NGRAPH) g_gcnt[i >> 8][i & 255] = 0;
}

// ---------------- CSR build ----------------
__global__ void k_hist(const int* __restrict__ el, const int* __restrict__ er) {
    int side = blockIdx.z;
    const int* edge = side ? er : el;
    int e = blockIdx.x * blockDim.x + threadIdx.x;
    if (e < NEDGES) atomicAdd(&g_cur[side][edge[NEDGES + e]], 1);
}

// single-block scan per side (1024 threads x 20 items, int4 loads)
__global__ void k_scan() {
    int side = blockIdx.x;
    __shared__ int wsum[32];
    int t = threadIdx.x, lane = t & 31, w = t >> 5;
    const int IT = 20;
    int base = t * IT;
    int vals[IT];
    int s = 0;
    if (base + IT <= NNODES) {
        const int4* p = (const int4*)(&g_cur[side][base]);
#pragma unroll
        for (int j = 0; j < 5; j++) {
            int4 v = p[j];
            vals[j * 4 + 0] = v.x; vals[j * 4 + 1] = v.y;
            vals[j * 4 + 2] = v.z; vals[j * 4 + 3] = v.w;
        }
#pragma unroll
        for (int j = 0; j < IT; j++) s += vals[j];
    } else {
#pragma unroll
        for (int j = 0; j < IT; j++) vals[j] = 0;
    }
    int ps = s;
    for (int o = 1; o < 32; o <<= 1) {
        int v = __shfl_up_sync(0xffffffffu, ps, o);
        if (lane >= o) ps += v;
    }
    if (lane == 31) wsum[w] = ps;
    __syncthreads();
    if (w == 0) {
        int v = wsum[lane];
        for (int o = 1; o < 32; o <<= 1) {
            int u = __shfl_up_sync(0xffffffffu, v, o);
            if (lane >= o) v += u;
        }
        wsum[lane] = v;
    }
    __syncthreads();
    int run = ps - s + (w > 0 ? wsum[w - 1] : 0);
    if (base + IT <= NNODES) {
#pragma unroll
        for (int j = 0; j < IT; j++) {
            int i = base + j;
            g_off[side][i] = run;
            g_cur[side][i] = run;
            run += vals[j];
        }
    }
    if (t == 1023) g_off[side][NNODES] = NEPLUS;
}

__global__ void k_scatter(const int* __restrict__ el, const int* __restrict__ er) {
    int side = blockIdx.z;
    const int* edge = side ? er : el;
    int e = blockIdx.x * blockDim.x + threadIdx.x;
    if (e < NEPLUS) {
        int s, d;
        if (e < NEDGES) { s = edge[e]; d = edge[NEDGES + e]; }
        else            { s = d = e - NEDGES; }
        int p = atomicAdd(&g_cur[side][d], 1);
        g_srcs[side][p] = s;
    }
}

// ---------------- layer-1 "GEMM" via table gather ----------------
__global__ void k_l1gather(const int* __restrict__ xl, const int* __restrict__ xr) {
    int side = blockIdx.z;
    const int* xi = side ? xr : xl;
    int idx = blockIdx.x * blockDim.x + threadIdx.x;
    if (idx >= NNODES * 128) return;
    int n = idx >> 7, q = idx & 127;
    int v = xi[n];
    float4 val = *(const float4*)(g_tab + v * 512 + q * 4);
    if (q < 64) {
        __half2 h0 = __floats2half2_rn(val.x, val.y);
        __half2 h1 = __floats2half2_rn(val.z, val.w);
        uint2 u = make_uint2(*(uint32_t*)&h0, *(uint32_t*)&h1);
        *(uint2*)(&g_xh[side][n * 256 + q * 4]) = u;
    } else {
        *(float4*)(&g_lin[side][n * 256 + (q - 64) * 4]) = val;
    }
    if (q == 0) {
        *(float4*)(&g_as[side][n * 4]) = *(const float4*)(g_tatt + v * 8);
        *(float4*)(&g_ad[side][n * 4]) = *(const float4*)(g_tatt + v * 8 + 4);
    }
}

// ---------------- tf32 tensor-core GEMM, dual output, cp.async double-buffer --------
__device__ __forceinline__ void mma_tf32(float* c, const unsigned* a, const unsigned* b) {
    asm volatile(
        "mma.sync.aligned.m16n8k8.row.col.f32.tf32.tf32.f32 "
        "{%0,%1,%2,%3},{%4,%5,%6,%7},{%8,%9},{%0,%1,%2,%3};"
        : "+f"(c[0]), "+f"(c[1]), "+f"(c[2]), "+f"(c[3])
        : "r"(a[0]), "r"(a[1]), "r"(a[2]), "r"(a[3]),
          "r"(b[0]), "r"(b[1]));
}

#define AS_STRIDE 36
#define BS_STRIDE 136
#define GEMM_SMEM ((2 * 128 * AS_STRIDE + 2 * 32 * BS_STRIDE) * 4)

// C1 target is __half (xh); C2 is float (lin). sC1/sC2 in elements.
__global__ __launch_bounds__(256) void gemm_dual(
    const float* __restrict__ Abase, long sA,
    const float* __restrict__ B1, __half* __restrict__ C1base, long sC1, int N1,
    const float* __restrict__ B2, float* __restrict__ C2base, long sC2, int N2,
    int M, int K) {
    extern __shared__ float smem[];
    float (*As)[128][AS_STRIDE] = (float (*)[128][AS_STRIDE])smem;
    float (*Bs)[32][BS_STRIDE] = (float (*)[32][BS_STRIDE])(smem + 2 * 128 * AS_STRIDE);

    int side = blockIdx.z;
    const float* A = Abase + (size_t)side * sA;
    int t1 = N1 >> 7;
    bool ishalf = ((int)blockIdx.x < t1);
    const float* B; int N, n0;
    __half* Ch = C1base + (size_t)side * sC1;
    float* Cf = C2base + (size_t)side * sC2;
    if (ishalf) { B = B1; N = N1; n0 = blockIdx.x << 7; }
    else        { B = B2; N = N2; n0 = (blockIdx.x - t1) << 7; }

    int tid = threadIdx.x;
    int warp = tid >> 5, lane = tid & 31;
    int m0 = blockIdx.y * 128;
    int wm = (warp >> 2) * 64;
    int wn = (warp & 3) * 32;
    int gid = lane >> 2, tig = lane & 3;

    int arow = tid >> 3, acq = (tid & 7) << 2;
    int bk = tid >> 5, bnq = (tid & 31) << 2;

    float c[4][4][4];
#pragma unroll
    for (int i = 0; i < 4; i++)
#pragma unroll
        for (int j = 0; j < 4; j++)
#pragma unroll
            for (int r = 0; r < 4; r++) c[i][j][r] = 0.f;

    auto load_tile = [&](int s, int kk) {
#pragma unroll
        for (int i = 0; i < 4; i++) {
            int row = arow + 32 * i;
            const float* asrc = A + (size_t)(m0 + row) * K + kk + acq;
            int sz = (m0 + row < M) ? 16 : 0;
            if (!sz) asrc = A;
            CPA(sptr(&As[s][row][acq]), asrc, sz);
            const float* bsrc = B + (size_t)(kk + bk + 8 * i) * N + n0 + bnq;
            CPA(sptr(&Bs[s][bk + 8 * i][bnq]), bsrc, 16);
        }
        CP_COMMIT();
    };

    auto compute = [&](int s) {
#pragma unroll
        for (int ks = 0; ks < 4; ks++) {
            int kb = ks * 8;
            unsigned a[4][4], b[4][2];
#pragma unroll
            for (int mi = 0; mi < 4; mi++) {
                int r = wm + mi * 16 + gid;
                a[mi][0] = tf32u(As[s][r][kb + tig]);
                a[mi][1] = tf32u(As[s][r + 8][kb + tig]);
                a[mi][2] = tf32u(As[s][r][kb + tig + 4]);
                a[mi][3] = tf32u(As[s][r + 8][kb + tig + 4]);
            }
#pragma unroll
            for (int ni = 0; ni < 4; ni++) {
                int cn = wn + ni * 8 + gid;
                b[ni][0] = tf32u(Bs[s][kb + tig][cn]);
                b[ni][1] = tf32u(Bs[s][kb + tig + 4][cn]);
            }
#pragma unroll
            for (int mi = 0; mi < 4; mi++)
#pragma unroll
                for (int ni = 0; ni < 4; ni++) mma_tf32(c[mi][ni], a[mi], b[ni]);
        }
    };

    int KT = K >> 5;
    load_tile(0, 0);
    for (int kt = 0; kt < KT; kt++) {
        if (kt + 1 < KT) {
            load_tile((kt + 1) & 1, (kt + 1) << 5);
            CP_WAIT1();
        } else {
            CP_WAIT0();
        }
        __syncthreads();
        compute(kt & 1);
        __syncthreads();
    }
#pragma unroll
    for (int mi = 0; mi < 4; mi++) {
#pragma unroll
        for (int ni = 0; ni < 4; ni++) {
            int r0 = m0 + wm + mi * 16 + gid;
            int cc = n0 + wn + ni * 8 + tig * 2;
            if (ishalf) {
                if (r0 < M)
                    *(__half2*)(Ch + (size_t)r0 * N + cc) =
                        __floats2half2_rn(c[mi][ni][0], c[mi][ni][1]);
                if (r0 + 8 < M)
                    *(__half2*)(Ch + (size_t)(r0 + 8) * N + cc) =
                        __floats2half2_rn(c[mi][ni][2], c[mi][ni][3]);
            } else {
                if (r0 < M)
                    *(float2*)(Cf + (size_t)r0 * N + cc) = make_float2(c[mi][ni][0], c[mi][ni][1]);
                if (r0 + 8 < M)
                    *(float2*)(Cf + (size_t)(r0 + 8) * N + cc) = make_float2(c[mi][ni][2], c[mi][ni][3]);
            }
        }
    }
}

// ---------------- attention scores (xh is half) ----------------
__global__ void k_att(const float* __restrict__ atts, const float* __restrict__ attd, int C) {
    int side = blockIdx.z;
    int gt = blockIdx.x * blockDim.x + threadIdx.x;
    int w = gt >> 5, lane = gt & 31;
    if (w >= NNODES * 4) return;
    int n = w >> 2, h = w & 3;
    const __half* xr = g_xh[side] + (size_t)n * 4 * C + h * C;
    float ss = 0.f, sd = 0.f;
    for (int c = lane; c < C; c += 32) {
        float v = __half2float(xr[c]);
        ss += v * atts[h * C + c];
        sd += v * attd[h * C + c];
    }
    for (int o = 16; o; o >>= 1) {
        ss += __shfl_xor_sync(0xffffffffu, ss, o);
        sd += __shfl_xor_sync(0xffffffffu, sd, o);
    }
    if (lane == 0) { g_as[side][n * 4 + h] = ss; g_ad[side][n * 4 + h] = sd; }
}

// ---------------- GAT aggregation, concat heads (C=64, F=256). warp per node --------
__global__ void k_gat_concat(const float* __restrict__ bias, const float* __restrict__ lbias,
                             int relu_flag) {
    int side = blockIdx.z;
    int gt = blockIdx.x * blockDim.x + threadIdx.x;
    int i = gt >> 5, lane = gt & 31;
    if (i >= NNODES) return;
    int beg = g_off[side][i], end = g_off[side][i + 1];
    float4 ad = *(const float4*)(&g_ad[side][(size_t)i * 4]);
    float m0 = -1e30f, m1 = -1e30f, m2 = -1e30f, m3 = -1e30f;
    for (int e = beg + lane; e < end; e += 32) {
        int s = g_srcs[side][e];
        float4 as = *(const float4*)(&g_as[side][(size_t)s * 4]);
        m0 = fmaxf(m0, lrelu(as.x + ad.x));
        m1 = fmaxf(m1, lrelu(as.y + ad.y));
        m2 = fmaxf(m2, lrelu(as.z + ad.z));
        m3 = fmaxf(m3, lrelu(as.w + ad.w));
    }
    for (int o = 16; o; o >>= 1) {
        m0 = fmaxf(m0, __shfl_xor_sync(0xffffffffu, m0, o));
        m1 = fmaxf(m1, __shfl_xor_sync(0xffffffffu, m1, o));
        m2 = fmaxf(m2, __shfl_xor_sync(0xffffffffu, m2, o));
        m3 = fmaxf(m3, __shfl_xor_sync(0xffffffffu, m3, o));
    }
    float z0 = 0.f, z1 = 0.f, z2 = 0.f, z3 = 0.f;
    for (int e = beg + lane; e < end; e += 32) {
        int s = g_srcs[side][e];
        float4 as = *(const float4*)(&g_as[side][(size_t)s * 4]);
        float e0 = __expf(lrelu(as.x + ad.x) - m0);
        float e1 = __expf(lrelu(as.y + ad.y) - m1);
        float e2 = __expf(lrelu(as.z + ad.z) - m2);
        float e3 = __expf(lrelu(as.w + ad.w) - m3);
        *(float4*)(&g_exp[side][(size_t)e * 4]) = make_float4(e0, e1, e2, e3);
        z0 += e0; z1 += e1; z2 += e2; z3 += e3;
    }
    for (int o = 16; o; o >>= 1) {
        z0 += __shfl_xor_sync(0xffffffffu, z0, o);
        z1 += __shfl_xor_sync(0xffffffffu, z1, o);
        z2 += __shfl_xor_sync(0xffffffffu, z2, o);
        z3 += __shfl_xor_sync(0xffffffffu, z3, o);
    }
    float i0 = 1.f / (z0 + 1e-16f), i1 = 1.f / (z1 + 1e-16f);
    float i2 = 1.f / (z2 + 1e-16f), i3 = 1.f / (z3 + 1e-16f);
    int h = lane >> 3;
    float myinv = (h == 0) ? i0 : (h == 1) ? i1 : (h == 2) ? i2 : i3;
    int col = lane * 8;   // 8 half columns per lane
    float a0 = 0.f, a1 = 0.f, a2 = 0.f, a3 = 0.f, a4 = 0.f, a5 = 0.f, a6 = 0.f, a7 = 0.f;
    for (int e = beg; e < end; e++) {
        int s = g_srcs[side][e];
        float w = g_exp[side][(size_t)e * 4 + h] * myinv;
        uint4 u = *(const uint4*)(g_xh[side] + (size_t)s * 256 + col);
        __half2* hp = (__half2*)&u;
        float2 f0 = __half22float2(hp[0]);
        float2 f1 = __half22float2(hp[1]);
        float2 f2 = __half22float2(hp[2]);
        float2 f3 = __half22float2(hp[3]);
        a0 += w * f0.x; a1 += w * f0.y; a2 += w * f1.x; a3 += w * f1.y;
        a4 += w * f2.x; a5 += w * f2.y; a6 += w * f3.x; a7 += w * f3.y;
    }
    float4 lr0 = *(const float4*)(g_lin[side] + (size_t)i * 256 + col);
    float4 lr1 = *(const float4*)(g_lin[side] + (size_t)i * 256 + col + 4);
    float4 b0 = *(const float4*)(bias + col);
    float4 b1 = *(const float4*)(bias + col + 4);
    float4 lb0 = *(const float4*)(lbias + col);
    float4 lb1 = *(const float4*)(lbias + col + 4);
    float4 o0, o1;
    o0.x = a0 + b0.x + lr0.x + lb0.x; o0.y = a1 + b0.y + lr0.y + lb0.y;
    o0.z = a2 + b0.z + lr0.z + lb0.z; o0.w = a3 + b0.w + lr0.w + lb0.w;
    o1.x = a4 + b1.x + lr1.x + lb1.x; o1.y = a5 + b1.y + lr1.y + lb1.y;
    o1.z = a6 + b1.z + lr1.z + lb1.z; o1.w = a7 + b1.w + lr1.w + lb1.w;
    if (relu_flag) {
        o0.x = fmaxf(o0.x, 0.f); o0.y = fmaxf(o0.y, 0.f);
        o0.z = fmaxf(o0.z, 0.f); o0.w = fmaxf(o0.w, 0.f);
        o1.x = fmaxf(o1.x, 0.f); o1.y = fmaxf(o1.y, 0.f);
        o1.z = fmaxf(o1.z, 0.f); o1.w = fmaxf(o1.w, 0.f);
    }
    *(float4*)(g_feat[side] + (size_t)i * 256 + col) = o0;
    *(float4*)(g_feat[side] + (size_t)i * 256 + col + 4) = o1;
}

// ---------------- GAT aggregation, mean over heads (C=128, F=512 -> 128) ------------
__global__ void k_gat_mean(const float* __restrict__ bias, const float* __restrict__ lbias) {
    int side = blockIdx.z;
    int gt = blockIdx.x * blockDim.x + threadIdx.x;
    int i = gt >> 5, lane = gt & 31;
    if (i >= NNODES) return;
    int beg = g_off[side][i], end = g_off[side][i + 1];
    float4 ad = *(const float4*)(&g_ad[side][(size_t)i * 4]);
    float m0 = -1e30f, m1 = -1e30f, m2 = -1e30f, m3 = -1e30f;
    for (int e = beg + lane; e < end; e += 32) {
        int s = g_srcs[side][e];
        float4 as = *(const float4*)(&g_as[side][(size_t)s * 4]);
        m0 = fmaxf(m0, lrelu(as.x + ad.x));
        m1 = fmaxf(m1, lrelu(as.y + ad.y));
        m2 = fmaxf(m2, lrelu(as.z + ad.z));
        m3 = fmaxf(m3, lrelu(as.w + ad.w));
    }
    for (int o = 16; o; o >>= 1) {
        m0 = fmaxf(m0, __shfl_xor_sync(0xffffffffu, m0, o));
        m1 = fmaxf(m1, __shfl_xor_sync(0xffffffffu, m1, o));
        m2 = fmaxf(m2, __shfl_xor_sync(0xffffffffu, m2, o));
        m3 = fmaxf(m3, __shfl_xor_sync(0xffffffffu, m3, o));
    }
    float z0 = 0.f, z1 = 0.f, z2 = 0.f, z3 = 0.f;
    for (int e = beg + lane; e < end; e += 32) {
        int s = g_srcs[side][e];
        float4 as = *(const float4*)(&g_as[side][(size_t)s * 4]);
        float e0 = __expf(lrelu(as.x + ad.x) - m0);
        float e1 = __expf(lrelu(as.y + ad.y) - m1);
        float e2 = __expf(lrelu(as.z + ad.z) - m2);
        float e3 = __expf(lrelu(as.w + ad.w) - m3);
        *(float4*)(&g_exp[side][(size_t)e * 4]) = make_float4(e0, e1, e2, e3);
        z0 += e0; z1 += e1; z2 += e2; z3 += e3;
    }
    for (int o = 16; o; o >>= 1) {
        z0 += __shfl_xor_sync(0xffffffffu, z0, o);
        z1 += __shfl_xor_sync(0xffffffffu, z1, o);
        z2 += __shfl_xor_sync(0xffffffffu, z2, o);
        z3 += __shfl_xor_sync(0xffffffffu, z3, o);
    }
    float i0 = 1.f / (z0 + 1e-16f), i1 = 1.f / (z1 + 1e-16f);
    float i2 = 1.f / (z2 + 1e-16f), i3 = 1.f / (z3 + 1e-16f);
    int h = lane >> 3;
    float myinv = (h == 0) ? i0 : (h == 1) ? i1 : (h == 2) ? i2 : i3;
    int col = lane * 16;   // 16 half columns per lane of the 512
    float acc[16];
#pragma unroll
    for (int j = 0; j < 16; j++) acc[j] = 0.f;
    for (int e = beg; e < end; e++) {
        int s = g_srcs[side][e];
        float w = g_exp[side][(size_t)e * 4 + h] * myinv;
        const uint4* xr = (const uint4*)(g_xh[side] + (size_t)s * 512 + col);
        uint4 u0 = xr[0], u1 = xr[1];
        __half2* hp0 = (__half2*)&u0;
        __half2* hp1 = (__half2*)&u1;
#pragma unroll
        for (int j = 0; j < 4; j++) {
            float2 f = __half22float2(hp0[j]);
            acc[j * 2] += w * f.x; acc[j * 2 + 1] += w * f.y;
        }
#pragma unroll
        for (int j = 0; j < 4; j++) {
            float2 f = __half22float2(hp1[j]);
            acc[8 + j * 2] += w * f.x; acc[8 + j * 2 + 1] += w * f.y;
        }
    }
#pragma unroll
    for (int mask = 8; mask <= 16; mask <<= 1)
#pragma unroll
        for (int j = 0; j < 16; j++)
            acc[j] += __shfl_xor_sync(0xffffffffu, acc[j], mask);
    if (lane < 8) {
        int c0 = lane * 16;
#pragma unroll
        for (int j = 0; j < 4; j++) {
            int c = c0 + j * 4;
            float4 lr = *(const float4*)(g_lin[side] + (size_t)i * 128 + c);
            float4 bb = *(const float4*)(bias + c);
            float4 lb = *(const float4*)(lbias + c);
            float4 o;
            o.x = 0.25f * acc[j * 4 + 0] + bb.x + lr.x + lb.x;
            o.y = 0.25f * acc[j * 4 + 1] + bb.y + lr.y + lb.y;
            o.z = 0.25f * acc[j * 4 + 2] + bb.z + lr.z + lb.z;
            o.w = 0.25f * acc[j * 4 + 3] + bb.w + lr.w + lb.w;
            *(float4*)(g_feat[side] + (size_t)i * 128 + c) = o;
        }
    }
}

// ---------------- global mean pool: run-length accumulation (batch sorted) ----------
#define POOL_NB 64
__global__ void k_pool_sum(const int* __restrict__ bl, const int* __restrict__ br, float* out) {
    int side = blockIdx.z;
    const int* batch = side ? br : bl;
    float* po = out + side * NGRAPH * 128;
    int n0 = blockIdx.x * POOL_NB;
    int c = threadIdx.x & 127;
    int r = threadIdx.x >> 7;   // 0/1, node stride 2
    float acc = 0.f;
    int cur = -1, cnt = 0;
    for (int j = r; j < POOL_NB; j += 2) {
        int n = n0 + j;
        if (n >= NNODES) break;
        int b = batch[n];
        if (b != cur) {
            if (cur >= 0) {
                atomicAdd(&po[cur * 128 + c], acc);
                if (c == 0) atomicAdd(&g_gcnt[side][cur], cnt);
            }
            acc = 0.f; cnt = 0; cur = b;
        }
        acc += g_feat[side][(size_t)n * 128 + c];
        cnt++;
    }
    if (cur >= 0) {
        atomicAdd(&po[cur * 128 + c], acc);
        if (c == 0) atomicAdd(&g_gcnt[side][cur], cnt);
    }
}
__global__ void k_pool_div(float* out) {
    int i = blockIdx.x * blockDim.x + threadIdx.x;
    if (i < 2 * NGRAPH * 128) {
        int side = i >> 15;
        float cnt = (float)g_gcnt[side][(i >> 7) & 255];
        out[i] /= fmaxf(cnt, 1.f);
    }
}

// ---------------- host orchestration ----------------
extern "C" void kernel_launch(void* const* d_in, const int* in_sizes, int n_in,
                              void* d_out, int out_size) {
    const int* x_l     = (const int*)d_in[0];
    const int* edge_l  = (const int*)d_in[1];
    const int* batch_l = (const int*)d_in[2];
    const int* x_r     = (const int*)d_in[3];
    const int* edge_r  = (const int*)d_in[4];
    const int* batch_r = (const int*)d_in[5];
    const float* emb = (const float*)d_in[6];
    const float* W1  = (const float*)d_in[7];  const float* as1 = (const float*)d_in[8];
    const float* ad1 = (const float*)d_in[9];  const float* b1  = (const float*)d_in[10];
    const float* lw1 = (const float*)d_in[11]; const float* lb1 = (const float*)d_in[12];
    const float* W2  = (const float*)d_in[13]; const float* as2 = (const float*)d_in[14];
    const float* ad2 = (const float*)d_in[15]; const float* b2  = (const float*)d_in[16];
    const float* lw2 = (const float*)d_in[17]; const float* lb2 = (const float*)d_in[18];
    const float* W3  = (const float*)d_in[19]; const float* as3 = (const float*)d_in[20];
    const float* ad3 = (const float*)d_in[21]; const float* b3  = (const float*)d_in[22];
    const float* lw3 = (const float*)d_in[23]; const float* lb3 = (const float*)d_in[24];
    float* out = (float*)d_out;

    float *feat, *lin;
    __half* xh;
    cudaGetSymbolAddress((void**)&feat, g_feat);
    cudaGetSymbolAddress((void**)&xh, g_xh);
    cudaGetSymbolAddress((void**)&lin, g_lin);

    cudaFuncSetAttribute(gemm_dual, cudaFuncAttributeMaxDynamicSharedMemorySize, GEMM_SMEM);

    const int TB = 256;
    const long sFeat = (long)NNODES * 256, sXh = (long)NNODES * 512, sLin = (long)NNODES * 256;
    const int MB = (NNODES + 127) / 128;
    int att_grid = (NNODES * 4 * 32 + TB - 1) / TB;
    int gat_grid = (NNODES * 32 + TB - 1) / TB;

    // precompute + init + CSR (both sides fused)
    k_pre<<<VOCAB, 256>>>(emb, W1, lw1, as1, ad1);
    k_init<<<(2 * NGRAPH * 128 + TB - 1) / TB, TB>>>(out);
    k_hist<<<dim3((NEDGES + TB - 1) / TB, 1, 2), TB>>>(edge_l, edge_r);
    k_scan<<<2, 1024>>>();
    k_scatter<<<dim3((NEPLUS + TB - 1) / TB, 1, 2), TB>>>(edge_l, edge_r);

    // Layer 1: table gather replaces GEMM + att
    k_l1gather<<<dim3((NNODES * 128 + TB - 1) / TB, 1, 2), TB>>>(x_l, x_r);
    k_gat_concat<<<dim3(gat_grid, 1, 2), TB>>>(b1, lb1, 1);

    // Layer 2 (256 -> 256)
    gemm_dual<<<dim3(4, MB, 2), 256, GEMM_SMEM>>>(feat, sFeat, W2, xh, sXh, 256,
                                                  lw2, lin, sLin, 256, NNODES, 256);
    k_att<<<dim3(att_grid, 1, 2), TB>>>(as2, ad2, 64);
    k_gat_concat<<<dim3(gat_grid, 1, 2), TB>>>(b2, lb2, 1);

    // Layer 3 (256 -> 512 xh / 128 lin)
    gemm_dual<<<dim3(5, MB, 2), 256, GEMM_SMEM>>>(feat, sFeat, W3, xh, sXh, 512,
                                                  lw3, lin, sLin, 128, NNODES, 256);
    k_att<<<dim3(att_grid, 1, 2), TB>>>(as3, ad3, 128);
    k_gat_mean<<<dim3(gat_grid, 1, 2), TB>>>(b3, lb3);

    // Pool
    k_pool_sum<<<dim3((NNODES + POOL_NB - 1) / POOL_NB, 1, 2), TB>>>(batch_l, batch_r, out);
    k_pool_div<<<(2 * NGRAPH * 128 + TB - 1) / TB, TB>>>(out);
}

// round 7
// speedup vs baseline: 3.4247x; 1.2340x over previous
#include <cuda_runtime.h>
#include <cuda_fp16.h>
#include <cstdint>

#define NNODES 20000
#define NEDGES 320000
#define NEPLUS 340000   // edges + self loops
#define NGRAPH 256
#define VOCAB  128
#define NWH    294912   // fp16 weights: W2(65536) lw2(65536) W3(131072) lw3(32768)

// ---------------- scratch (device globals; no runtime alloc allowed) ----------------
__device__ float  g_feat [2][NNODES * 128];  // layer-3 output (fp32, pooled)
__device__ __half g_feath[2][NNODES * 256];  // concat-layer outputs (GEMM inputs)
__device__ __half g_xh   [2][NNODES * 512];  // fp16 message features
__device__ float  g_lin  [2][NNODES * 256];
__device__ float  g_as   [2][NNODES * 4];
__device__ float  g_ad   [2][NNODES * 4];
__device__ float  g_exp  [2][NEPLUS * 4];
__device__ int    g_off  [2][NNODES + 1];
__device__ int    g_cur  [2][NNODES];
__device__ int    g_srcs [2][NEPLUS];
__device__ int    g_gcnt [2][NGRAPH];
__device__ int    g_bsum [2][128];
__device__ float  g_tab  [VOCAB * 512];
__device__ float  g_tatt [VOCAB * 8];
__device__ __half g_wh   [NWH];

__device__ __forceinline__ float lrelu(float x) { return x > 0.f ? x : 0.2f * x; }

__device__ __forceinline__ uint32_t sptr(const void* p) {
    return (uint32_t)__cvta_generic_to_shared(p);
}
#define CPA(dst, src, sz) \
    asm volatile("cp.async.cg.shared.global [%0], [%1], 16, %2;" :: "r"(dst), "l"(src), "r"(sz))
#define CP_COMMIT() asm volatile("cp.async.commit_group;" ::: "memory")
#define CP_WAIT1()  asm volatile("cp.async.wait_group 1;" ::: "memory")
#define CP_WAIT0()  asm volatile("cp.async.wait_group 0;" ::: "memory")

// ---------------- weight fp32->fp16 conversion ----------------
__global__ void k_wconv(const float* __restrict__ W2, const float* __restrict__ lw2,
                        const float* __restrict__ W3, const float* __restrict__ lw3) {
    int i = blockIdx.x * blockDim.x + threadIdx.x;
    if (i >= NWH) return;
    float v;
    if (i < 65536)       v = W2[i];
    else if (i < 131072) v = lw2[i - 65536];
    else if (i < 262144) v = W3[i - 131072];
    else                 v = lw3[i - 262144];
    g_wh[i] = __float2half_rn(v);
}

// ---------------- layer-1 precompute: tables over the 128-entry vocab ----------------
__global__ void k_pre(const float* __restrict__ emb, const float* __restrict__ W1,
                      const float* __restrict__ lw1, const float* __restrict__ as1,
                      const float* __restrict__ ad1) {
    __shared__ float er[128];
    __shared__ float sAs[4], sAd[4];
    int v = blockIdx.x, t = threadIdx.x;  // 256 threads
    if (t < 128) er[t] = emb[v * 128 + t];
    if (t < 4) { sAs[t] = 0.f; sAd[t] = 0.f; }
    __syncthreads();
    float acc0 = 0.f, acc1 = 0.f;
    for (int k = 0; k < 128; k++) {
        float e = er[k];
        acc0 += e * W1[k * 256 + t];
        acc1 += e * lw1[k * 256 + t];
    }
    g_tab[v * 512 + t] = acc0;
    g_tab[v * 512 + 256 + t] = acc1;
    int h = t >> 6, c = t & 63;
    atomicAdd(&sAs[h], acc0 * as1[h * 64 + c]);
    atomicAdd(&sAd[h], acc0 * ad1[h * 64 + c]);
    __syncthreads();
    if (t < 4) { g_tatt[v * 8 + t] = sAs[t]; g_tatt[v * 8 + 4 + t] = sAd[t]; }
}

// ---------------- init: CSR counts (self loop), pool accumulators, out ----------------
__global__ void k_init(float* out) {
    int i = blockIdx.x * blockDim.x + threadIdx.x;
    if (i < 2 * NNODES) g_cur[i / NNODES][i % NNODES] = 1;
    if (i < 2 * NGRAPH * 128) out[i] = 0.f;
    if (i < 2 * NGRAPH) g_gcnt[i >> 8][i & 255] = 0;
}

// ---------------- CSR build ----------------
__global__ void k_hist(const int* __restrict__ el, const int* __restrict__ er) {
    int side = blockIdx.z;
    const int* edge = side ? er : el;
    int e = blockIdx.x * blockDim.x + threadIdx.x;
    if (e < NEDGES) atomicAdd(&g_cur[side][edge[NEDGES + e]], 1);
}

__global__ void k_scan_a() {
    int side = blockIdx.z;
    __shared__ int sh[256];
    int t = threadIdx.x, i = blockIdx.x * 256 + t;
    int v = (i < NNODES) ? g_cur[side][i] : 0;
    sh[t] = v;
    __syncthreads();
    for (int o = 1; o < 256; o <<= 1) {
        int x = (t >= o) ? sh[t - o] : 0;
        __syncthreads();
        sh[t] += x;
        __syncthreads();
    }
    if (i < NNODES) g_off[side][i] = sh[t] - v;
    if (t == 255) g_bsum[side][blockIdx.x] = sh[255];
}
__global__ void k_scan_b() {   // grid=2, 32 threads: scan 79 block sums
    int side = blockIdx.x, lane = threadIdx.x;
    int v[3]; int s = 0;
#pragma unroll
    for (int j = 0; j < 3; j++) {
        int b = lane * 3 + j;
        v[j] = (b < 79) ? g_bsum[side][b] : 0;
        s += v[j];
    }
    int ps = s;
    for (int o = 1; o < 32; o <<= 1) {
        int u = __shfl_up_sync(0xffffffffu, ps, o);
        if (lane >= o) ps += u;
    }
    int run = ps - s;
#pragma unroll
    for (int j = 0; j < 3; j++) {
        int b = lane * 3 + j;
        if (b < 79) g_bsum[side][b] = run;
        run += v[j];
    }
}
__global__ void k_scan_c() {
    int side = blockIdx.z;
    int i = blockIdx.x * 256 + threadIdx.x;
    if (i < NNODES) {
        int o = g_off[side][i] + g_bsum[side][i >> 8];
        g_off[side][i] = o;
        g_cur[side][i] = o;
    }
    if (i == 0) g_off[side][NNODES] = NEPLUS;
}

__global__ void k_scatter(const int* __restrict__ el, const int* __restrict__ er) {
    int side = blockIdx.z;
    const int* edge = side ? er : el;
    int e = blockIdx.x * blockDim.x + threadIdx.x;
    if (e < NEPLUS) {
        int s, d;
        if (e < NEDGES) { s = edge[e]; d = edge[NEDGES + e]; }
        else            { s = d = e - NEDGES; }
        int p = atomicAdd(&g_cur[side][d], 1);
        g_srcs[side][p] = s;
    }
}

// ---------------- layer-1 "GEMM" via table gather ----------------
__global__ void k_l1gather(const int* __restrict__ xl, const int* __restrict__ xr) {
    int side = blockIdx.z;
    const int* xi = side ? xr : xl;
    int idx = blockIdx.x * blockDim.x + threadIdx.x;
    if (idx >= NNODES * 128) return;
    int n = idx >> 7, q = idx & 127;
    int v = xi[n];
    float4 val = *(const float4*)(g_tab + v * 512 + q * 4);
    if (q < 64) {
        __half2 h0 = __floats2half2_rn(val.x, val.y);
        __half2 h1 = __floats2half2_rn(val.z, val.w);
        uint2 u = make_uint2(*(uint32_t*)&h0, *(uint32_t*)&h1);
        *(uint2*)(&g_xh[side][n * 256 + q * 4]) = u;
    } else {
        *(float4*)(&g_lin[side][n * 256 + (q - 64) * 4]) = val;
    }
    if (q == 0) {
        *(float4*)(&g_as[side][n * 4]) = *(const float4*)(g_tatt + v * 8);
        *(float4*)(&g_ad[side][n * 4]) = *(const float4*)(g_tatt + v * 8 + 4);
    }
}

// ---------------- fp16 tensor-core GEMM, dual output, cp.async double-buffer --------
__device__ __forceinline__ void mma_f16(float* c, const unsigned* a, const unsigned* b) {
    asm volatile(
        "mma.sync.aligned.m16n8k16.row.col.f32.f16.f16.f32 "
        "{%0,%1,%2,%3},{%4,%5,%6,%7},{%8,%9},{%0,%1,%2,%3};"
        : "+f"(c[0]), "+f"(c[1]), "+f"(c[2]), "+f"(c[3])
        : "r"(a[0]), "r"(a[1]), "r"(a[2]), "r"(a[3]),
          "r"(b[0]), "r"(b[1]));
}

#define AS_STRIDE 40    // halves; 80B row stride -> conflict-free ldmatrix
#define BS_STRIDE 136   // halves; 272B row stride -> conflict-free ldmatrix
#define GEMM_SMEM ((2 * 128 * AS_STRIDE + 2 * 32 * BS_STRIDE) * 2)

__global__ __launch_bounds__(256) void gemm_dual(
    const __half* __restrict__ Abase, long sA,
    const __half* __restrict__ B1, __half* __restrict__ C1base, long sC1, int N1,
    const __half* __restrict__ B2, float* __restrict__ C2base, long sC2, int N2,
    int M, int K) {
    extern __shared__ __half smh[];
    __half (*As)[128][AS_STRIDE] = (__half (*)[128][AS_STRIDE])smh;
    __half (*Bs)[32][BS_STRIDE] = (__half (*)[32][BS_STRIDE])(smh + 2 * 128 * AS_STRIDE);

    int side = blockIdx.z;
    const __half* A = Abase + (size_t)side * sA;
    int t1 = N1 >> 7;
    bool ishalf = ((int)blockIdx.x < t1);
    const __half* B; int N, n0;
    __half* Ch = C1base + (size_t)side * sC1;
    float* Cf = C2base + (size_t)side * sC2;
    if (ishalf) { B = B1; N = N1; n0 = blockIdx.x << 7; }
    else        { B = B2; N = N2; n0 = (blockIdx.x - t1) << 7; }

    int tid = threadIdx.x;
    int warp = tid >> 5, lane = tid & 31;
    int m0 = blockIdx.y * 128;
    int wm = (warp >> 2) * 64;
    int wn = (warp & 3) * 32;
    int gid = lane >> 2, tig = lane & 3;

    float c[4][4][4];
#pragma unroll
    for (int i = 0; i < 4; i++)
#pragma unroll
        for (int j = 0; j < 4; j++)
#pragma unroll
            for (int r = 0; r < 4; r++) c[i][j][r] = 0.f;

    auto load_tile = [&](int s, int kk) {
#pragma unroll
        for (int i = 0; i < 2; i++) {
            int cid = tid + 256 * i;
            int row = cid >> 2, coff = (cid & 3) * 8;     // A: 128 rows x 32 halves
            const __half* asrc = A + (size_t)(m0 + row) * K + kk + coff;
            int sz = (m0 + row < M) ? 16 : 0;
            if (!sz) asrc = A;
            CPA(sptr(&As[s][row][coff]), asrc, sz);
            int krow = cid >> 4, noff = (cid & 15) * 8;   // B: 32 rows x 128 halves
            const __half* bsrc = B + (size_t)(kk + krow) * N + n0 + noff;
            CPA(sptr(&Bs[s][krow][noff]), bsrc, 16);
        }
        CP_COMMIT();
    };

    auto compute = [&](int s) {
#pragma unroll
        for (int ks = 0; ks < 2; ks++) {
            unsigned a[4][4], b[4][2];
#pragma unroll
            for (int mi = 0; mi < 4; mi++) {
                uint32_t addr = sptr(&As[s][wm + mi * 16 + (lane & 15)][ks * 16 + (lane >> 4) * 8]);
                asm volatile("ldmatrix.sync.aligned.m8n8.x4.shared.b16 {%0,%1,%2,%3}, [%4];"
                             : "=r"(a[mi][0]), "=r"(a[mi][1]), "=r"(a[mi][2]), "=r"(a[mi][3])
                             : "r"(addr));
            }
#pragma unroll
            for (int ni = 0; ni < 4; ni++) {
                uint32_t addr = sptr(&Bs[s][ks * 16 + (lane & 15)][wn + ni * 8]);
                asm volatile("ldmatrix.sync.aligned.m8n8.x2.trans.shared.b16 {%0,%1}, [%2];"
                             : "=r"(b[ni][0]), "=r"(b[ni][1])
                             : "r"(addr));
            }
#pragma unroll
            for (int mi = 0; mi < 4; mi++)
#pragma unroll
                for (int ni = 0; ni < 4; ni++) mma_f16(c[mi][ni], a[mi], b[ni]);
        }
    };

    int KT = K >> 5;
    load_tile(0, 0);
    for (int kt = 0; kt < KT; kt++) {
        if (kt + 1 < KT) {
            load_tile((kt + 1) & 1, (kt + 1) << 5);
            CP_WAIT1();
        } else {
            CP_WAIT0();
        }
        __syncthreads();
        compute(kt & 1);
        __syncthreads();
    }
#pragma unroll
    for (int mi = 0; mi < 4; mi++) {
#pragma unroll
        for (int ni = 0; ni < 4; ni++) {
            int r0 = m0 + wm + mi * 16 + gid;
            int cc = n0 + wn + ni * 8 + tig * 2;
            if (ishalf) {
                if (r0 < M)
                    *(__half2*)(Ch + (size_t)r0 * N + cc) =
                        __floats2half2_rn(c[mi][ni][0], c[mi][ni][1]);
                if (r0 + 8 < M)
                    *(__half2*)(Ch + (size_t)(r0 + 8) * N + cc) =
                        __floats2half2_rn(c[mi][ni][2], c[mi][ni][3]);
            } else {
                if (r0 < M)
                    *(float2*)(Cf + (size_t)r0 * N + cc) = make_float2(c[mi][ni][0], c[mi][ni][1]);
                if (r0 + 8 < M)
                    *(float2*)(Cf + (size_t)(r0 + 8) * N + cc) = make_float2(c[mi][ni][2], c[mi][ni][3]);
            }
        }
    }
}

// ---------------- attention scores (xh is half) ----------------
__global__ void k_att(const float* __restrict__ atts, const float* __restrict__ attd, int C) {
    int side = blockIdx.z;
    int gt = blockIdx.x * blockDim.x + threadIdx.x;
    int w = gt >> 5, lane = gt & 31;
    if (w >= NNODES * 4) return;
    int n = w >> 2, h = w & 3;
    const __half* xr = g_xh[side] + (size_t)n * 4 * C + h * C;
    float ss = 0.f, sd = 0.f;
    for (int c = lane; c < C; c += 32) {
        float v = __half2float(xr[c]);
        ss += v * atts[h * C + c];
        sd += v * attd[h * C + c];
    }
    for (int o = 16; o; o >>= 1) {
        ss += __shfl_xor_sync(0xffffffffu, ss, o);
        sd += __shfl_xor_sync(0xffffffffu, sd, o);
    }
    if (lane == 0) { g_as[side][n * 4 + h] = ss; g_ad[side][n * 4 + h] = sd; }
}

// ---------------- GAT aggregation, concat heads (C=64, F=256). warp per node --------
__global__ void k_gat_concat(const float* __restrict__ bias, const float* __restrict__ lbias,
                             int relu_flag) {
    int side = blockIdx.z;
    int gt = blockIdx.x * blockDim.x + threadIdx.x;
    int i = gt >> 5, lane = gt & 31;
    if (i >= NNODES) return;
    int beg = g_off[side][i], end = g_off[side][i + 1];
    float4 ad = *(const float4*)(&g_ad[side][(size_t)i * 4]);
    float m0 = -1e30f, m1 = -1e30f, m2 = -1e30f, m3 = -1e30f;
    for (int e = beg + lane; e < end; e += 32) {
        int s = g_srcs[side][e];
        float4 as = *(const float4*)(&g_as[side][(size_t)s * 4]);
        m0 = fmaxf(m0, lrelu(as.x + ad.x));
        m1 = fmaxf(m1, lrelu(as.y + ad.y));
        m2 = fmaxf(m2, lrelu(as.z + ad.z));
        m3 = fmaxf(m3, lrelu(as.w + ad.w));
    }
    for (int o = 16; o; o >>= 1) {
        m0 = fmaxf(m0, __shfl_xor_sync(0xffffffffu, m0, o));
        m1 = fmaxf(m1, __shfl_xor_sync(0xffffffffu, m1, o));
        m2 = fmaxf(m2, __shfl_xor_sync(0xffffffffu, m2, o));
        m3 = fmaxf(m3, __shfl_xor_sync(0xffffffffu, m3, o));
    }
    float z0 = 0.f, z1 = 0.f, z2 = 0.f, z3 = 0.f;
    for (int e = beg + lane; e < end; e += 32) {
        int s = g_srcs[side][e];
        float4 as = *(const float4*)(&g_as[side][(size_t)s * 4]);
        float e0 = __expf(lrelu(as.x + ad.x) - m0);
        float e1 = __expf(lrelu(as.y + ad.y) - m1);
        float e2 = __expf(lrelu(as.z + ad.z) - m2);
        float e3 = __expf(lrelu(as.w + ad.w) - m3);
        *(float4*)(&g_exp[side][(size_t)e * 4]) = make_float4(e0, e1, e2, e3);
        z0 += e0; z1 += e1; z2 += e2; z3 += e3;
    }
    for (int o = 16; o; o >>= 1) {
        z0 += __shfl_xor_sync(0xffffffffu, z0, o);
        z1 += __shfl_xor_sync(0xffffffffu, z1, o);
        z2 += __shfl_xor_sync(0xffffffffu, z2, o);
        z3 += __shfl_xor_sync(0xffffffffu, z3, o);
    }
    float i0 = 1.f / (z0 + 1e-16f), i1 = 1.f / (z1 + 1e-16f);
    float i2 = 1.f / (z2 + 1e-16f), i3 = 1.f / (z3 + 1e-16f);
    int h = lane >> 3;
    float myinv = (h == 0) ? i0 : (h == 1) ? i1 : (h == 2) ? i2 : i3;
    int col = lane * 8;
    float a0 = 0.f, a1 = 0.f, a2 = 0.f, a3 = 0.f, a4 = 0.f, a5 = 0.f, a6 = 0.f, a7 = 0.f;
    for (int e = beg; e < end; e++) {
        int s = g_srcs[side][e];
        float w = g_exp[side][(size_t)e * 4 + h] * myinv;
        uint4 u = *(const uint4*)(g_xh[side] + (size_t)s * 256 + col);
        __half2* hp = (__half2*)&u;
        float2 f0 = __half22float2(hp[0]);
        float2 f1 = __half22float2(hp[1]);
        float2 f2 = __half22float2(hp[2]);
        float2 f3 = __half22float2(hp[3]);
        a0 += w * f0.x; a1 += w * f0.y; a2 += w * f1.x; a3 += w * f1.y;
        a4 += w * f2.x; a5 += w * f2.y; a6 += w * f3.x; a7 += w * f3.y;
    }
    float4 lr0 = *(const float4*)(g_lin[side] + (size_t)i * 256 + col);
    float4 lr1 = *(const float4*)(g_lin[side] + (size_t)i * 256 + col + 4);
    float4 b0 = *(const float4*)(bias + col);
    float4 b1 = *(const float4*)(bias + col + 4);
    float4 lb0 = *(const float4*)(lbias + col);
    float4 lb1 = *(const float4*)(lbias + col + 4);
    float o0x = a0 + b0.x + lr0.x + lb0.x, o0y = a1 + b0.y + lr0.y + lb0.y;
    float o0z = a2 + b0.z + lr0.z + lb0.z, o0w = a3 + b0.w + lr0.w + lb0.w;
    float o1x = a4 + b1.x + lr1.x + lb1.x, o1y = a5 + b1.y + lr1.y + lb1.y;
    float o1z = a6 + b1.z + lr1.z + lb1.z, o1w = a7 + b1.w + lr1.w + lb1.w;
    if (relu_flag) {
        o0x = fmaxf(o0x, 0.f); o0y = fmaxf(o0y, 0.f);
        o0z = fmaxf(o0z, 0.f); o0w = fmaxf(o0w, 0.f);
        o1x = fmaxf(o1x, 0.f); o1y = fmaxf(o1y, 0.f);
        o1z = fmaxf(o1z, 0.f); o1w = fmaxf(o1w, 0.f);
    }
    __half2 h0 = __floats2half2_rn(o0x, o0y);
    __half2 h1 = __floats2half2_rn(o0z, o0w);
    __half2 h2 = __floats2half2_rn(o1x, o1y);
    __half2 h3 = __floats2half2_rn(o1z, o1w);
    uint4 uo = make_uint4(*(uint32_t*)&h0, *(uint32_t*)&h1, *(uint32_t*)&h2, *(uint32_t*)&h3);
    *(uint4*)(&g_feath[side][(size_t)i * 256 + col]) = uo;
}

// ---------------- GAT aggregation, mean over heads (C=128, F=512 -> 128) ------------
__global__ void k_gat_mean(const float* __restrict__ bias, const float* __restrict__ lbias) {
    int side = blockIdx.z;
    int gt = blockIdx.x * blockDim.x + threadIdx.x;
    int i = gt >> 5, lane = gt & 31;
    if (i >= NNODES) return;
    int beg = g_off[side][i], end = g_off[side][i + 1];
    float4 ad = *(const float4*)(&g_ad[side][(size_t)i * 4]);
    float m0 = -1e30f, m1 = -1e30f, m2 = -1e30f, m3 = -1e30f;
    for (int e = beg + lane; e < end; e += 32) {
        int s = g_srcs[side][e];
        float4 as = *(const float4*)(&g_as[side][(size_t)s * 4]);
        m0 = fmaxf(m0, lrelu(as.x + ad.x));
        m1 = fmaxf(m1, lrelu(as.y + ad.y));
        m2 = fmaxf(m2, lrelu(as.z + ad.z));
        m3 = fmaxf(m3, lrelu(as.w + ad.w));
    }
    for (int o = 16; o; o >>= 1) {
        m0 = fmaxf(m0, __shfl_xor_sync(0xffffffffu, m0, o));
        m1 = fmaxf(m1, __shfl_xor_sync(0xffffffffu, m1, o));
        m2 = fmaxf(m2, __shfl_xor_sync(0xffffffffu, m2, o));
        m3 = fmaxf(m3, __shfl_xor_sync(0xffffffffu, m3, o));
    }
    float z0 = 0.f, z1 = 0.f, z2 = 0.f, z3 = 0.f;
    for (int e = beg + lane; e < end; e += 32) {
        int s = g_srcs[side][e];
        float4 as = *(const float4*)(&g_as[side][(size_t)s * 4]);
        float e0 = __expf(lrelu(as.x + ad.x) - m0);
        float e1 = __expf(lrelu(as.y + ad.y) - m1);
        float e2 = __expf(lrelu(as.z + ad.z) - m2);
        float e3 = __expf(lrelu(as.w + ad.w) - m3);
        *(float4*)(&g_exp[side][(size_t)e * 4]) = make_float4(e0, e1, e2, e3);
        z0 += e0; z1 += e1; z2 += e2; z3 += e3;
    }
    for (int o = 16; o; o >>= 1) {
        z0 += __shfl_xor_sync(0xffffffffu, z0, o);
        z1 += __shfl_xor_sync(0xffffffffu, z1, o);
        z2 += __shfl_xor_sync(0xffffffffu, z2, o);
        z3 += __shfl_xor_sync(0xffffffffu, z3, o);
    }
    float i0 = 1.f / (z0 + 1e-16f), i1 = 1.f / (z1 + 1e-16f);
    float i2 = 1.f / (z2 + 1e-16f), i3 = 1.f / (z3 + 1e-16f);
    int h = lane >> 3;
    float myinv = (h == 0) ? i0 : (h == 1) ? i1 : (h == 2) ? i2 : i3;
    int col = lane * 16;
    float acc[16];
#pragma unroll
    for (int j = 0; j < 16; j++) acc[j] = 0.f;
    for (int e = beg; e < end; e++) {
        int s = g_srcs[side][e];
        float w = g_exp[side][(size_t)e * 4 + h] * myinv;
        const uint4* xr = (const uint4*)(g_xh[side] + (size_t)s * 512 + col);
        uint4 u0 = xr[0], u1 = xr[1];
        __half2* hp0 = (__half2*)&u0;
        __half2* hp1 = (__half2*)&u1;
#pragma unroll
        for (int j = 0; j < 4; j++) {
            float2 f = __half22float2(hp0[j]);
            acc[j * 2] += w * f.x; acc[j * 2 + 1] += w * f.y;
        }
#pragma unroll
        for (int j = 0; j < 4; j++) {
            float2 f = __half22float2(hp1[j]);
            acc[8 + j * 2] += w * f.x; acc[8 + j * 2 + 1] += w * f.y;
        }
    }
#pragma unroll
    for (int mask = 8; mask <= 16; mask <<= 1)
#pragma unroll
        for (int j = 0; j < 16; j++)
            acc[j] += __shfl_xor_sync(0xffffffffu, acc[j], mask);
    if (lane < 8) {
        int c0 = lane * 16;
#pragma unroll
        for (int j = 0; j < 4; j++) {
            int c = c0 + j * 4;
            float4 lr = *(const float4*)(g_lin[side] + (size_t)i * 128 + c);
            float4 bb = *(const float4*)(bias + c);
            float4 lb = *(const float4*)(lbias + c);
            float4 o;
            o.x = 0.25f * acc[j * 4 + 0] + bb.x + lr.x + lb.x;
            o.y = 0.25f * acc[j * 4 + 1] + bb.y + lr.y + lb.y;
            o.z = 0.25f * acc[j * 4 + 2] + bb.z + lr.z + lb.z;
            o.w = 0.25f * acc[j * 4 + 3] + bb.w + lr.w + lb.w;
            *(float4*)(g_feat[side] + (size_t)i * 128 + c) = o;
        }
    }
}

// ---------------- global mean pool: run-length accumulation (batch sorted) ----------
#define POOL_NB 64
__global__ void k_pool_sum(const int* __restrict__ bl, const int* __restrict__ br, float* out) {
    int side = blockIdx.z;
    const int* batch = side ? br : bl;
    float* po = out + side * NGRAPH * 128;
    int n0 = blockIdx.x * POOL_NB;
    int c = threadIdx.x & 127;
    int r = threadIdx.x >> 7;
    float acc = 0.f;
    int cur = -1, cnt = 0;
    for (int j = r; j < POOL_NB; j += 2) {
        int n = n0 + j;
        if (n >= NNODES) break;
        int b = batch[n];
        if (b != cur) {
            if (cur >= 0) {
                atomicAdd(&po[cur * 128 + c], acc);
                if (c == 0) atomicAdd(&g_gcnt[side][cur], cnt);
            }
            acc = 0.f; cnt = 0; cur = b;
        }
        acc += g_feat[side][(size_t)n * 128 + c];
        cnt++;
    }
    if (cur >= 0) {
        atomicAdd(&po[cur * 128 + c], acc);
        if (c == 0) atomicAdd(&g_gcnt[side][cur], cnt);
    }
}
__global__ void k_pool_div(float* out) {
    int i = blockIdx.x * blockDim.x + threadIdx.x;
    if (i < 2 * NGRAPH * 128) {
        int side = i >> 15;
        float cnt = (float)g_gcnt[side][(i >> 7) & 255];
        out[i] /= fmaxf(cnt, 1.f);
    }
}

// ---------------- host orchestration ----------------
extern "C" void kernel_launch(void* const* d_in, const int* in_sizes, int n_in,
                              void* d_out, int out_size) {
    const int* x_l     = (const int*)d_in[0];
    const int* edge_l  = (const int*)d_in[1];
    const int* batch_l = (const int*)d_in[2];
    const int* x_r     = (const int*)d_in[3];
    const int* edge_r  = (const int*)d_in[4];
    const int* batch_r = (const int*)d_in[5];
    const float* emb = (const float*)d_in[6];
    const float* W1  = (const float*)d_in[7];  const float* as1 = (const float*)d_in[8];
    const float* ad1 = (const float*)d_in[9];  const float* b1  = (const float*)d_in[10];
    const float* lw1 = (const float*)d_in[11]; const float* lb1 = (const float*)d_in[12];
    const float* W2  = (const float*)d_in[13]; const float* as2 = (const float*)d_in[14];
    const float* ad2 = (const float*)d_in[15]; const float* b2  = (const float*)d_in[16];
    const float* lw2 = (const float*)d_in[17]; const float* lb2 = (const float*)d_in[18];
    const float* W3  = (const float*)d_in[19]; const float* as3 = (const float*)d_in[20];
    const float* ad3 = (const float*)d_in[21]; const float* b3  = (const float*)d_in[22];
    const float* lw3 = (const float*)d_in[23]; const float* lb3 = (const float*)d_in[24];
    float* out = (float*)d_out;

    __half *feath, *xh, *wh;
    float *lin;
    cudaGetSymbolAddress((void**)&feath, g_feath);
    cudaGetSymbolAddress((void**)&xh, g_xh);
    cudaGetSymbolAddress((void**)&lin, g_lin);
    cudaGetSymbolAddress((void**)&wh, g_wh);

    cudaFuncSetAttribute(gemm_dual, cudaFuncAttributeMaxDynamicSharedMemorySize, GEMM_SMEM);

    const int TB = 256;
    const long sFeat = (long)NNODES * 256, sXh = (long)NNODES * 512, sLin = (long)NNODES * 256;
    const int MB = (NNODES + 127) / 128;
    int att_grid = (NNODES * 4 * 32 + TB - 1) / TB;
    int gat_grid = (NNODES * 32 + TB - 1) / TB;

    // precompute + init + CSR (both sides fused)
    k_wconv<<<(NWH + TB - 1) / TB, TB>>>(W2, lw2, W3, lw3);
    k_pre<<<VOCAB, 256>>>(emb, W1, lw1, as1, ad1);
    k_init<<<(2 * NGRAPH * 128 + TB - 1) / TB, TB>>>(out);
    k_hist<<<dim3((NEDGES + TB - 1) / TB, 1, 2), TB>>>(edge_l, edge_r);
    k_scan_a<<<dim3(79, 1, 2), 256>>>();
    k_scan_b<<<2, 32>>>();
    k_scan_c<<<dim3(79, 1, 2), 256>>>();
    k_scatter<<<dim3((NEPLUS + TB - 1) / TB, 1, 2), TB>>>(edge_l, edge_r);

    // Layer 1: table gather replaces GEMM + att
    k_l1gather<<<dim3((NNODES * 128 + TB - 1) / TB, 1, 2), TB>>>(x_l, x_r);
    k_gat_concat<<<dim3(gat_grid, 1, 2), TB>>>(b1, lb1, 1);

    // Layer 2 (256 -> 256): A = feath fp16, W fp16
    gemm_dual<<<dim3(4, MB, 2), 256, GEMM_SMEM>>>(feath, sFeat, wh, xh, sXh, 256,
                                                  wh + 65536, lin, sLin, 256, NNODES, 256);
    k_att<<<dim3(att_grid, 1, 2), TB>>>(as2, ad2, 64);
    k_gat_concat<<<dim3(gat_grid, 1, 2), TB>>>(b2, lb2, 1);

    // Layer 3 (256 -> 512 xh / 128 lin)
    gemm_dual<<<dim3(5, MB, 2), 256, GEMM_SMEM>>>(feath, sFeat, wh + 131072, xh, sXh, 512,
                                                  wh + 262144, lin, sLin, 128, NNODES, 256);
    k_att<<<dim3(att_grid, 1, 2), TB>>>(as3, ad3, 128);
    k_gat_mean<<<dim3(gat_grid, 1, 2), TB>>>(b3, lb3);

    // Pool
    k_pool_sum<<<dim3((NNODES + POOL_NB - 1) / POOL_NB, 1, 2), TB>>>(batch_l, batch_r, out);
    k_pool_div<<<(2 * NGRAPH * 128 + TB - 1) / TB, TB>>>(out);
}